// round 13
// baseline (speedup 1.0000x reference)
#include <cuda_runtime.h>
#include <cuda_bf16.h>
#include <cstdint>
#include <cmath>

#define BATCH 4
#define SEQ   2048
#define EMB   1024
#define HEADS 16
#define HDIM  64
#define MROWS (BATCH*SEQ)   // 8192

// Scratch (no allocations allowed)
__device__ float g_q[BATCH*HEADS*SEQ*HDIM];
__device__ float g_k[BATCH*HEADS*SEQ*HDIM];
__device__ float g_v[BATCH*HEADS*SEQ*HDIM];
__device__ float g_ao[BATCH*SEQ*EMB];

// ---------------------------------------------------------------------------
// helpers
// ---------------------------------------------------------------------------
__device__ __forceinline__ uint32_t tf32_rna(float x) {
    uint32_t r;
    asm("cvt.rna.tf32.f32 %0, %1;" : "=r"(r) : "f"(x));
    return r;
}
__device__ __forceinline__ float4 cvt4(float4 v) {
    v.x = __uint_as_float(tf32_rna(v.x));
    v.y = __uint_as_float(tf32_rna(v.y));
    v.z = __uint_as_float(tf32_rna(v.z));
    v.w = __uint_as_float(tf32_rna(v.w));
    return v;
}
__device__ __forceinline__ void mma_tf32(float* c, const uint32_t* a, const uint32_t* b) {
    asm volatile(
        "mma.sync.aligned.m16n8k8.row.col.f32.tf32.tf32.f32 "
        "{%0,%1,%2,%3}, {%4,%5,%6,%7}, {%8,%9}, {%0,%1,%2,%3};"
        : "+f"(c[0]), "+f"(c[1]), "+f"(c[2]), "+f"(c[3])
        : "r"(a[0]), "r"(a[1]), "r"(a[2]), "r"(a[3]), "r"(b[0]), "r"(b[1]));
}
__device__ __forceinline__ void mma_bf16(float* c, const uint32_t* a, const uint32_t* b) {
    asm volatile(
        "mma.sync.aligned.m16n8k16.row.col.f32.bf16.bf16.f32 "
        "{%0,%1,%2,%3}, {%4,%5,%6,%7}, {%8,%9}, {%0,%1,%2,%3};"
        : "+f"(c[0]), "+f"(c[1]), "+f"(c[2]), "+f"(c[3])
        : "r"(a[0]), "r"(a[1]), "r"(a[2]), "r"(a[3]), "r"(b[0]), "r"(b[1]));
}
// split x0,x1 into bf16 hi/lo pairs packed as uint32 (x0 in low half, x1 in high)
__device__ __forceinline__ void bf16split2(float x0, float x1, uint32_t& hi, uint32_t& lo) {
    __nv_bfloat16 h0 = __float2bfloat16_rn(x0);
    __nv_bfloat16 h1 = __float2bfloat16_rn(x1);
    float r0 = x0 - __bfloat162float(h0);
    float r1 = x1 - __bfloat162float(h1);
    __nv_bfloat16 l0 = __float2bfloat16_rn(r0);
    __nv_bfloat16 l1 = __float2bfloat16_rn(r1);
    hi = ((uint32_t)__bfloat16_as_ushort(h1) << 16) | (uint32_t)__bfloat16_as_ushort(h0);
    lo = ((uint32_t)__bfloat16_as_ushort(l1) << 16) | (uint32_t)__bfloat16_as_ushort(l0);
}

// ---------------------------------------------------------------------------
// 3xBF16 GEMM body, double-buffered packed SMEM. (unchanged from R12)
// ---------------------------------------------------------------------------
#define GSTG 5248   // uint32 per stage: 2*128*12 + 2*8*136
#define SAh(st,r,p) smu[(st)*GSTG          + (r)*12  + (p)]
#define SAl(st,r,p) smu[(st)*GSTG + 1536   + (r)*12  + (p)]
#define SBh(st,p,c) smu[(st)*GSTG + 3072   + (p)*136 + (c)]
#define SBl(st,p,c) smu[(st)*GSTG + 4160   + (p)*136 + (c)]
#define GEMM_SMEM_BYTES (2*GSTG*4)

__device__ __forceinline__ void gemm_body(
    const float* __restrict__ A, const float* __restrict__ Bm,
    const float* __restrict__ bias, float* __restrict__ C,
    int headsplit, uint32_t* smu)
{
    const int K = EMB, N = EMB;
    const int tid  = threadIdx.x;
    const int wid  = tid >> 5;
    const int lane = tid & 31;
    const int gid  = lane >> 2;
    const int tig  = lane & 3;
    const int wm   = wid >> 1;
    const int wn   = wid & 1;
    const int row0 = blockIdx.y * 128;
    const int col0 = blockIdx.x * 128;

    float c[2][8][4];
#pragma unroll
    for (int mt = 0; mt < 2; mt++)
#pragma unroll
        for (int nt = 0; nt < 8; nt++)
#pragma unroll
            for (int i = 0; i < 4; i++) c[mt][nt][i] = 0.f;

    const int ar = tid >> 1, ac = (tid & 1) * 8, ap0 = (tid & 1) * 4;
    const int br = tid >> 5, bc = (tid & 31) * 4;

    const float* Abase  = A + (size_t)(row0 + ar) * K + ac;
    const float* Bbase0 = Bm + (size_t)(2*br    ) * N + col0 + bc;
    const float* Bbase1 = Bm + (size_t)(2*br + 1) * N + col0 + bc;

    float4 aR0 = *(const float4*)(Abase);
    float4 aR1 = *(const float4*)(Abase + 4);
    float4 bRa = *(const float4*)(Bbase0);
    float4 bRb = *(const float4*)(Bbase1);

    // stage 0
    {
        uint32_t h[4], l[4];
        bf16split2(aR0.x, aR0.y, h[0], l[0]);
        bf16split2(aR0.z, aR0.w, h[1], l[1]);
        bf16split2(aR1.x, aR1.y, h[2], l[2]);
        bf16split2(aR1.z, aR1.w, h[3], l[3]);
        *(uint4*)&SAh(0, ar, ap0) = make_uint4(h[0], h[1], h[2], h[3]);
        *(uint4*)&SAl(0, ar, ap0) = make_uint4(l[0], l[1], l[2], l[3]);
        bf16split2(bRa.x, bRb.x, h[0], l[0]);
        bf16split2(bRa.y, bRb.y, h[1], l[1]);
        bf16split2(bRa.z, bRb.z, h[2], l[2]);
        bf16split2(bRa.w, bRb.w, h[3], l[3]);
        *(uint4*)&SBh(0, br, bc) = make_uint4(h[0], h[1], h[2], h[3]);
        *(uint4*)&SBl(0, br, bc) = make_uint4(l[0], l[1], l[2], l[3]);
    }
    __syncthreads();

    int cur = 0;
    for (int k0 = 0; k0 < K; k0 += 16) {
        const bool more = (k0 + 16 < K);
        if (more) {
            aR0 = *(const float4*)(Abase + k0 + 16);
            aR1 = *(const float4*)(Abase + k0 + 20);
            bRa = *(const float4*)(Bbase0 + (size_t)(k0 + 16) * N);
            bRb = *(const float4*)(Bbase1 + (size_t)(k0 + 16) * N);
        }

        uint32_t ahi[2][4], alo[2][4];
#pragma unroll
        for (int mt = 0; mt < 2; mt++) {
            const int m0 = wm * 32 + mt * 16;
            ahi[mt][0] = SAh(cur, m0 + gid,     tig);
            ahi[mt][1] = SAh(cur, m0 + gid + 8, tig);
            ahi[mt][2] = SAh(cur, m0 + gid,     tig + 4);
            ahi[mt][3] = SAh(cur, m0 + gid + 8, tig + 4);
            alo[mt][0] = SAl(cur, m0 + gid,     tig);
            alo[mt][1] = SAl(cur, m0 + gid + 8, tig);
            alo[mt][2] = SAl(cur, m0 + gid,     tig + 4);
            alo[mt][3] = SAl(cur, m0 + gid + 8, tig + 4);
        }
#pragma unroll
        for (int nt = 0; nt < 8; nt++) {
            const int n0 = wn * 64 + nt * 8;
            uint32_t bh[2], bl[2];
            bh[0] = SBh(cur, tig,     n0 + gid);
            bh[1] = SBh(cur, tig + 4, n0 + gid);
            bl[0] = SBl(cur, tig,     n0 + gid);
            bl[1] = SBl(cur, tig + 4, n0 + gid);
#pragma unroll
            for (int mt = 0; mt < 2; mt++) {
                mma_bf16(c[mt][nt], ahi[mt], bh);
                mma_bf16(c[mt][nt], alo[mt], bh);
                mma_bf16(c[mt][nt], ahi[mt], bl);
            }
        }

        if (more) {
            const int nxt = cur ^ 1;
            uint32_t h[4], l[4];
            bf16split2(aR0.x, aR0.y, h[0], l[0]);
            bf16split2(aR0.z, aR0.w, h[1], l[1]);
            bf16split2(aR1.x, aR1.y, h[2], l[2]);
            bf16split2(aR1.z, aR1.w, h[3], l[3]);
            *(uint4*)&SAh(nxt, ar, ap0) = make_uint4(h[0], h[1], h[2], h[3]);
            *(uint4*)&SAl(nxt, ar, ap0) = make_uint4(l[0], l[1], l[2], l[3]);
            bf16split2(bRa.x, bRb.x, h[0], l[0]);
            bf16split2(bRa.y, bRb.y, h[1], l[1]);
            bf16split2(bRa.z, bRb.z, h[2], l[2]);
            bf16split2(bRa.w, bRb.w, h[3], l[3]);
            *(uint4*)&SBh(nxt, br, bc) = make_uint4(h[0], h[1], h[2], h[3]);
            *(uint4*)&SBl(nxt, br, bc) = make_uint4(l[0], l[1], l[2], l[3]);
            __syncthreads();
            cur = nxt;
        }
    }

#pragma unroll
    for (int mt = 0; mt < 2; mt++) {
        const int m_lo = row0 + wm * 32 + mt * 16 + gid;
        const int m_hi = m_lo + 8;
#pragma unroll
        for (int nt = 0; nt < 8; nt++) {
            const int n = col0 + wn * 64 + nt * 8 + 2 * tig;
            const float b0 = bias[n], b1 = bias[n + 1];
            float v00 = c[mt][nt][0] + b0, v01 = c[mt][nt][1] + b1;
            float v10 = c[mt][nt][2] + b0, v11 = c[mt][nt][3] + b1;
            if (headsplit) {
                const int b_lo = m_lo / SEQ, s_lo = m_lo % SEQ;
                const int b_hi = m_hi / SEQ, s_hi = m_hi % SEQ;
                const int h = n / HDIM, d = n % HDIM;
                C[(((size_t)(b_lo*HEADS + h))*SEQ + s_lo)*HDIM + d    ] = v00;
                C[(((size_t)(b_lo*HEADS + h))*SEQ + s_lo)*HDIM + d + 1] = v01;
                C[(((size_t)(b_hi*HEADS + h))*SEQ + s_hi)*HDIM + d    ] = v10;
                C[(((size_t)(b_hi*HEADS + h))*SEQ + s_hi)*HDIM + d + 1] = v11;
            } else {
                C[(size_t)m_lo * N + n    ] = v00;
                C[(size_t)m_lo * N + n + 1] = v01;
                C[(size_t)m_hi * N + n    ] = v10;
                C[(size_t)m_hi * N + n + 1] = v11;
            }
        }
    }
}

// merged Q/K/V projections: blockIdx.z selects weight/bias/output
__global__ __launch_bounds__(256)
void gemm_proj(const float* __restrict__ A,
               const float* __restrict__ W0, const float* __restrict__ W1,
               const float* __restrict__ W2,
               const float* __restrict__ b0, const float* __restrict__ b1,
               const float* __restrict__ b2,
               float* __restrict__ C0, float* __restrict__ C1, float* __restrict__ C2)
{
    extern __shared__ __align__(16) uint32_t smu[];
    const int z = blockIdx.z;
    const float* W = (z == 0) ? W0 : (z == 1) ? W1 : W2;
    const float* b = (z == 0) ? b0 : (z == 1) ? b1 : b2;
    float*       C = (z == 0) ? C0 : (z == 1) ? C1 : C2;
    gemm_body(A, W, b, C, 1, smu);
}

__global__ __launch_bounds__(256)
void gemm_out(const float* __restrict__ A, const float* __restrict__ W,
              const float* __restrict__ b, float* __restrict__ C)
{
    extern __shared__ __align__(16) uint32_t smu[];
    gemm_body(A, W, b, C, 0, smu);
}

// ---------------------------------------------------------------------------
// Causal flash attention v4, single-pass TF32, double-buffered K/V staging,
// exp2-domain softmax.
// Block: 128 q-rows, 128 threads, 4 warps; warp owns 32 rows (2 m-tiles).
// ---------------------------------------------------------------------------
#define QS(r,c)       sQ[(r)*68 + (c)]
#define KS_(st,r,c)   sK[(st)*(32*68) + (r)*68 + (c)]
#define VS_(st,r,c)   sV[(st)*(32*72) + (r)*72 + (c)]
#define SSW(cc,rr)    sP[(cc)*40 + (rr)]

#define ATTN_SMEM_FLOATS (128*68 + 2*32*68 + 2*32*72 + 4*32*40)
#define QSCALE (0.125f * 1.44269504088896340736f)   // 1/sqrt(D) * log2(e)

__global__ __launch_bounds__(128)
void attn_tf32(const float* __restrict__ Q, const float* __restrict__ Kg,
               const float* __restrict__ Vg, float* __restrict__ O)
{
    extern __shared__ __align__(16) float smem[];
    float* sQ  = smem;                     // 128 x 68
    float* sK  = sQ + 128*68;              // 2 x 32 x 68
    float* sV  = sK + 2*32*68;             // 2 x 32 x 72
    float* sPb = sV + 2*32*72;             // 4 warps x (32 cols x 40)

    const int bh  = blockIdx.y;
    const int qt  = blockIdx.x;
    const int tid = threadIdx.x;
    const int wid = tid >> 5;
    const int lane = tid & 31;
    const int gid = lane >> 2;
    const int tig = lane & 3;
    const int m0  = wid * 32;
    float* sP = sPb + wid * (32*40);

    const float* Qbase = Q + ((size_t)bh * SEQ + qt * 128) * HDIM;
    const float* Kbase = Kg + (size_t)bh * SEQ * HDIM;
    const float* Vbase = Vg + (size_t)bh * SEQ * HDIM;

    // stage Q (128x64), scaled by 1/sqrt(D)*log2e, cvt to tf32
    {
        const float* qr = Qbase + (size_t)tid * HDIM;
#pragma unroll
        for (int i = 0; i < 16; i++) {
            float4 v = *(const float4*)(qr + i * 4);
            v.x *= QSCALE; v.y *= QSCALE; v.z *= QSCALE; v.w *= QSCALE;
            *(float4*)&QS(tid, i * 4) = cvt4(v);
        }
    }

    float o[2][8][4];
#pragma unroll
    for (int mt = 0; mt < 2; mt++)
#pragma unroll
        for (int nt = 0; nt < 8; nt++)
#pragma unroll
            for (int i = 0; i < 4; i++) o[mt][nt][i] = 0.f;
    float mrow[2][2] = {{-INFINITY,-INFINITY},{-INFINITY,-INFINITY}};
    float lrow[2][2] = {{0.f,0.f},{0.f,0.f}};

    const int qmax_warp = qt * 128 + m0 + 31;
    const int nch = 4 * qt + 4;

    // staging coords: thread -> K/V row kr, cols kc..kc+15
    const int kr = tid >> 2, kc = (tid & 3) * 16;

    // preload chunk 0 and stage it
    float4 kreg[4], vreg[4];
    {
        const float* kp = Kbase + (size_t)kr * HDIM + kc;
        const float* vp = Vbase + (size_t)kr * HDIM + kc;
#pragma unroll
        for (int i = 0; i < 4; i++) {
            kreg[i] = *(const float4*)(kp + i * 4);
            vreg[i] = *(const float4*)(vp + i * 4);
        }
#pragma unroll
        for (int i = 0; i < 4; i++) {
            *(float4*)&KS_(0, kr, kc + i * 4) = cvt4(kreg[i]);
            *(float4*)&VS_(0, kr, kc + i * 4) = cvt4(vreg[i]);
        }
    }
    __syncthreads();

    int cur = 0;
    for (int ch = 0; ch < nch; ch++) {
        const bool more = (ch + 1 < nch);
        // prefetch next chunk into registers (hidden behind compute)
        if (more) {
            const float* kp = Kbase + (size_t)((ch + 1) * 32 + kr) * HDIM + kc;
            const float* vp = Vbase + (size_t)((ch + 1) * 32 + kr) * HDIM + kc;
#pragma unroll
            for (int i = 0; i < 4; i++) {
                kreg[i] = *(const float4*)(kp + i * 4);
                vreg[i] = *(const float4*)(vp + i * 4);
            }
        }

        if (ch * 32 <= qmax_warp) {
            // ---- S = Q K^T : 32 rows x 32 keys per warp ----
            float s[2][4][4];
#pragma unroll
            for (int mt = 0; mt < 2; mt++)
#pragma unroll
                for (int nt = 0; nt < 4; nt++)
#pragma unroll
                    for (int i = 0; i < 4; i++) s[mt][nt][i] = 0.f;

#pragma unroll
            for (int ks = 0; ks < 8; ks++) {
                uint32_t a[2][4];
#pragma unroll
                for (int mt = 0; mt < 2; mt++) {
                    const int r0 = m0 + mt * 16;
                    a[mt][0] = __float_as_uint(QS(r0 + gid,     ks*8 + tig));
                    a[mt][1] = __float_as_uint(QS(r0 + gid + 8, ks*8 + tig));
                    a[mt][2] = __float_as_uint(QS(r0 + gid,     ks*8 + tig + 4));
                    a[mt][3] = __float_as_uint(QS(r0 + gid + 8, ks*8 + tig + 4));
                }
#pragma unroll
                for (int nt = 0; nt < 4; nt++) {
                    uint32_t b[2];
                    b[0] = __float_as_uint(KS_(cur, nt*8 + gid, ks*8 + tig));
                    b[1] = __float_as_uint(KS_(cur, nt*8 + gid, ks*8 + tig + 4));
                    mma_tf32(s[0][nt], a[0], b);
                    mma_tf32(s[1][nt], a[1], b);
                }
            }

            // ---- register online softmax (log2 domain) ----
#pragma unroll
            for (int mt = 0; mt < 2; mt++) {
#pragma unroll
                for (int half = 0; half < 2; half++) {
                    const int qrow = qt * 128 + m0 + mt * 16 + gid + half * 8;
                    const int cb   = ch * 32 + 2 * tig;
                    float mx = -INFINITY;
#pragma unroll
                    for (int nt = 0; nt < 4; nt++) {
#pragma unroll
                        for (int ii = 0; ii < 2; ii++) {
                            const int cc = cb + nt * 8 + ii;
                            if (cc <= qrow)
                                mx = fmaxf(mx, s[mt][nt][half * 2 + ii]);
                        }
                    }
                    mx = fmaxf(mx, __shfl_xor_sync(0xffffffffu, mx, 1));
                    mx = fmaxf(mx, __shfl_xor_sync(0xffffffffu, mx, 2));
                    const float mold = mrow[mt][half];
                    const float mnew = fmaxf(mold, mx);
                    const float msafe = (mnew == -INFINITY) ? 0.f : mnew;
                    const float corr  = (mold == -INFINITY) ? 0.f : exp2f(mold - msafe);
                    float sum = 0.f;
#pragma unroll
                    for (int nt = 0; nt < 4; nt++) {
#pragma unroll
                        for (int ii = 0; ii < 2; ii++) {
                            const int cc = cb + nt * 8 + ii;
                            float p = (cc <= qrow) ? exp2f(s[mt][nt][half*2+ii] - msafe) : 0.f;
                            s[mt][nt][half*2+ii] = p;
                            sum += p;
                        }
                    }
                    sum += __shfl_xor_sync(0xffffffffu, sum, 1);
                    sum += __shfl_xor_sync(0xffffffffu, sum, 2);
                    lrow[mt][half] = lrow[mt][half] * corr + sum;
                    mrow[mt][half] = mnew;
#pragma unroll
                    for (int nt = 0; nt < 8; nt++) {
                        o[mt][nt][half*2+0] *= corr;
                        o[mt][nt][half*2+1] *= corr;
                    }
                }
            }

            // ---- write P (tf32-cvt'd) to per-warp buffer [col][row] stride 40 ----
#pragma unroll
            for (int mt = 0; mt < 2; mt++) {
                const int rl = mt * 16 + gid;
#pragma unroll
                for (int nt = 0; nt < 4; nt++) {
                    const int cc = nt * 8 + 2 * tig;
                    SSW(cc,     rl)     = __uint_as_float(tf32_rna(s[mt][nt][0]));
                    SSW(cc + 1, rl)     = __uint_as_float(tf32_rna(s[mt][nt][1]));
                    SSW(cc,     rl + 8) = __uint_as_float(tf32_rna(s[mt][nt][2]));
                    SSW(cc + 1, rl + 8) = __uint_as_float(tf32_rna(s[mt][nt][3]));
                }
            }
            __syncwarp();

            // ---- O += P V ----
#pragma unroll
            for (int ks = 0; ks < 4; ks++) {
                uint32_t p[2][4];
#pragma unroll
                for (int mt = 0; mt < 2; mt++) {
                    const int rl = mt * 16 + gid;
                    p[mt][0] = __float_as_uint(SSW(ks*8 + tig,     rl));
                    p[mt][1] = __float_as_uint(SSW(ks*8 + tig,     rl + 8));
                    p[mt][2] = __float_as_uint(SSW(ks*8 + tig + 4, rl));
                    p[mt][3] = __float_as_uint(SSW(ks*8 + tig + 4, rl + 8));
                }
#pragma unroll
                for (int nt = 0; nt < 8; nt++) {
                    uint32_t v[2];
                    v[0] = __float_as_uint(VS_(cur, ks*8 + tig,     nt*8 + gid));
                    v[1] = __float_as_uint(VS_(cur, ks*8 + tig + 4, nt*8 + gid));
                    mma_tf32(o[0][nt], p[0], v);
                    mma_tf32(o[1][nt], p[1], v);
                }
            }
        }

        if (more) {
            const int nxt = cur ^ 1;
#pragma unroll
            for (int i = 0; i < 4; i++) {
                *(float4*)&KS_(nxt, kr, kc + i * 4) = cvt4(kreg[i]);
                *(float4*)&VS_(nxt, kr, kc + i * 4) = cvt4(vreg[i]);
            }
            __syncthreads();
            cur = nxt;
        }
    }

    // epilogue: normalize and store to [b][s][h*64+d]
    const int b = bh / HEADS, h = bh % HEADS;
#pragma unroll
    for (int mt = 0; mt < 2; mt++) {
#pragma unroll
        for (int half = 0; half < 2; half++) {
            const float inv = 1.f / lrow[mt][half];
            const int sg = qt * 128 + m0 + mt * 16 + gid + half * 8;
            float* orow = O + ((size_t)(b * SEQ + sg)) * EMB + h * HDIM;
#pragma unroll
            for (int nt = 0; nt < 8; nt++) {
                const int cc = nt * 8 + 2 * tig;
                orow[cc]     = o[mt][nt][half*2+0] * inv;
                orow[cc + 1] = o[mt][nt][half*2+1] * inv;
            }
        }
    }
}

// ---------------------------------------------------------------------------
extern "C" void kernel_launch(void* const* d_in, const int* in_sizes, int n_in,
                              void* d_out, int out_size)
{
    const float* x  = (const float*)d_in[0];
    const float* Wq = (const float*)d_in[1];
    const float* bq = (const float*)d_in[2];
    const float* Wk = (const float*)d_in[3];
    const float* bk = (const float*)d_in[4];
    const float* Wv = (const float*)d_in[5];
    const float* bv = (const float*)d_in[6];
    const float* Wo = (const float*)d_in[7];
    const float* bo = (const float*)d_in[8];
    float* out = (float*)d_out;

    float *q_ptr, *k_ptr, *v_ptr, *ao_ptr;
    cudaGetSymbolAddress((void**)&q_ptr,  g_q);
    cudaGetSymbolAddress((void**)&k_ptr,  g_k);
    cudaGetSymbolAddress((void**)&v_ptr,  g_v);
    cudaGetSymbolAddress((void**)&ao_ptr, g_ao);

    const int attn_smem = ATTN_SMEM_FLOATS * 4;
    static int attr_set = 0;
    if (!attr_set) {
        cudaFuncSetAttribute(attn_tf32,  cudaFuncAttributeMaxDynamicSharedMemorySize, attn_smem);
        cudaFuncSetAttribute(gemm_proj,  cudaFuncAttributeMaxDynamicSharedMemorySize, GEMM_SMEM_BYTES);
        cudaFuncSetAttribute(gemm_out,   cudaFuncAttributeMaxDynamicSharedMemorySize, GEMM_SMEM_BYTES);
        attr_set = 1;
    }

    dim3 gblk(256);
    dim3 pgrid(EMB / 128, MROWS / 128, 3);   // (8, 64, 3)
    gemm_proj<<<pgrid, gblk, GEMM_SMEM_BYTES>>>(x, Wq, Wk, Wv, bq, bk, bv,
                                                q_ptr, k_ptr, v_ptr);

    dim3 agrid(SEQ / 128, BATCH * HEADS);    // (16, 64)
    attn_tf32<<<agrid, 128, attn_smem>>>(q_ptr, k_ptr, v_ptr, ao_ptr);

    dim3 ogrid(EMB / 128, MROWS / 128, 1);   // (8, 64)
    gemm_out<<<ogrid, gblk, GEMM_SMEM_BYTES>>>(ao_ptr, Wo, bo, out);
}

// round 14
// speedup vs baseline: 1.1161x; 1.1161x over previous
#include <cuda_runtime.h>
#include <cuda_bf16.h>
#include <cstdint>
#include <cmath>

#define BATCH 4
#define SEQ   2048
#define EMB   1024
#define HEADS 16
#define HDIM  64
#define MROWS (BATCH*SEQ)   // 8192
#define KPAIRS (EMB/2)      // 512

// Scratch (no allocations allowed)
__device__ float g_q[BATCH*HEADS*SEQ*HDIM];
__device__ float g_k[BATCH*HEADS*SEQ*HDIM];
__device__ float g_v[BATCH*HEADS*SEQ*HDIM];
__device__ float g_ao[BATCH*SEQ*EMB];
// pre-split bf16 hi/lo planes (packed pairs as u32)
__device__ uint32_t g_xh[MROWS*KPAIRS],  g_xl[MROWS*KPAIRS];    // x   [m][k/2]
__device__ uint32_t g_aoh[MROWS*KPAIRS], g_aol[MROWS*KPAIRS];   // ao  [m][k/2]
__device__ uint32_t g_wh[4*KPAIRS*EMB],  g_wl[4*KPAIRS*EMB];    // W   [k/2][n] x4

// ---------------------------------------------------------------------------
// helpers
// ---------------------------------------------------------------------------
__device__ __forceinline__ uint32_t tf32_rna(float x) {
    uint32_t r;
    asm("cvt.rna.tf32.f32 %0, %1;" : "=r"(r) : "f"(x));
    return r;
}
__device__ __forceinline__ float4 cvt4(float4 v) {
    v.x = __uint_as_float(tf32_rna(v.x));
    v.y = __uint_as_float(tf32_rna(v.y));
    v.z = __uint_as_float(tf32_rna(v.z));
    v.w = __uint_as_float(tf32_rna(v.w));
    return v;
}
__device__ __forceinline__ void mma_tf32(float* c, const uint32_t* a, const uint32_t* b) {
    asm volatile(
        "mma.sync.aligned.m16n8k8.row.col.f32.tf32.tf32.f32 "
        "{%0,%1,%2,%3}, {%4,%5,%6,%7}, {%8,%9}, {%0,%1,%2,%3};"
        : "+f"(c[0]), "+f"(c[1]), "+f"(c[2]), "+f"(c[3])
        : "r"(a[0]), "r"(a[1]), "r"(a[2]), "r"(a[3]), "r"(b[0]), "r"(b[1]));
}
__device__ __forceinline__ void mma_bf16(float* c, const uint32_t* a, const uint32_t* b) {
    asm volatile(
        "mma.sync.aligned.m16n8k16.row.col.f32.bf16.bf16.f32 "
        "{%0,%1,%2,%3}, {%4,%5,%6,%7}, {%8,%9}, {%0,%1,%2,%3};"
        : "+f"(c[0]), "+f"(c[1]), "+f"(c[2]), "+f"(c[3])
        : "r"(a[0]), "r"(a[1]), "r"(a[2]), "r"(a[3]), "r"(b[0]), "r"(b[1]));
}
__device__ __forceinline__ void bf16split2(float x0, float x1, uint32_t& hi, uint32_t& lo) {
    __nv_bfloat16 h0 = __float2bfloat16_rn(x0);
    __nv_bfloat16 h1 = __float2bfloat16_rn(x1);
    float r0 = x0 - __bfloat162float(h0);
    float r1 = x1 - __bfloat162float(h1);
    __nv_bfloat16 l0 = __float2bfloat16_rn(r0);
    __nv_bfloat16 l1 = __float2bfloat16_rn(r1);
    hi = ((uint32_t)__bfloat16_as_ushort(h1) << 16) | (uint32_t)__bfloat16_as_ushort(h0);
    lo = ((uint32_t)__bfloat16_as_ushort(l1) << 16) | (uint32_t)__bfloat16_as_ushort(l0);
}

// ---------------------------------------------------------------------------
// pre-split kernels
// ---------------------------------------------------------------------------
// pack along the contiguous dim: src [M][K] fp32 -> planes [M][K/2] u32
__global__ __launch_bounds__(256)
void split_pairs(const float* __restrict__ src, uint32_t* __restrict__ hp,
                 uint32_t* __restrict__ lp, int n_pairs)
{
    int i = blockIdx.x * blockDim.x + threadIdx.x;
    if (i >= n_pairs) return;
    const float2 v = ((const float2*)src)[i];
    uint32_t h, l;
    bf16split2(v.x, v.y, h, l);
    hp[i] = h; lp[i] = l;
}

// weights: W [K][N] -> planes [K/2][N]; grid.y selects which weight
__global__ __launch_bounds__(256)
void split_w(const float* __restrict__ W0, const float* __restrict__ W1,
             const float* __restrict__ W2, const float* __restrict__ W3,
             uint32_t* __restrict__ hp, uint32_t* __restrict__ lp)
{
    const int z = blockIdx.y;
    const float* W = (z == 0) ? W0 : (z == 1) ? W1 : (z == 2) ? W2 : W3;
    int i = blockIdx.x * blockDim.x + threadIdx.x;   // over KPAIRS*EMB
    const int kp = i >> 10, n = i & (EMB - 1);
    const float a = W[((size_t)(2*kp))   * EMB + n];
    const float b = W[((size_t)(2*kp+1)) * EMB + n];
    uint32_t h, l;
    bf16split2(a, b, h, l);
    hp[(size_t)z * KPAIRS * EMB + i] = h;
    lp[(size_t)z * KPAIRS * EMB + i] = l;
}

// ---------------------------------------------------------------------------
// 3xBF16 GEMM body reading pre-split planes. Tile 128x128x16, 256 thr, 8 warps.
// SMEM (u32): A [row 128][k-pair 8] stride 12, B [k-pair 8][col 128] stride 136.
// ---------------------------------------------------------------------------
#define GSTG 5248
#define SAh(st,r,p) smu[(st)*GSTG          + (r)*12  + (p)]
#define SAl(st,r,p) smu[(st)*GSTG + 1536   + (r)*12  + (p)]
#define SBh(st,p,c) smu[(st)*GSTG + 3072   + (p)*136 + (c)]
#define SBl(st,p,c) smu[(st)*GSTG + 4160   + (p)*136 + (c)]
#define GEMM_SMEM_BYTES (2*GSTG*4)

__device__ __forceinline__ void gemm_body(
    const uint32_t* __restrict__ Ah, const uint32_t* __restrict__ Al,
    const uint32_t* __restrict__ Bh, const uint32_t* __restrict__ Bl,
    const float* __restrict__ bias, float* __restrict__ C,
    int headsplit, uint32_t* smu)
{
    const int N = EMB;
    const int tid  = threadIdx.x;
    const int wid  = tid >> 5;
    const int lane = tid & 31;
    const int gid  = lane >> 2;
    const int tig  = lane & 3;
    const int wm   = wid >> 1;
    const int wn   = wid & 1;
    const int row0 = blockIdx.y * 128;
    const int col0 = blockIdx.x * 128;

    float c[2][8][4];
#pragma unroll
    for (int mt = 0; mt < 2; mt++)
#pragma unroll
        for (int nt = 0; nt < 8; nt++)
#pragma unroll
            for (int i = 0; i < 4; i++) c[mt][nt][i] = 0.f;

    // A staging: thread -> row ar, k-pairs apo..apo+3
    const int ar = tid >> 1, apo = (tid & 1) * 4;
    // B staging: thread -> k-pair bp, cols bc4..bc4+3
    const int bp = tid >> 5, bc4 = (tid & 31) * 4;

    const uint32_t* Ahb = Ah + (size_t)(row0 + ar) * KPAIRS + apo;
    const uint32_t* Alb = Al + (size_t)(row0 + ar) * KPAIRS + apo;
    const uint32_t* Bhb = Bh + (size_t)bp * N + col0 + bc4;
    const uint32_t* Blb = Bl + (size_t)bp * N + col0 + bc4;

    uint4 a_h = *(const uint4*)(Ahb);
    uint4 a_l = *(const uint4*)(Alb);
    uint4 b_h = *(const uint4*)(Bhb);
    uint4 b_l = *(const uint4*)(Blb);

    // stage 0
    *(uint4*)&SAh(0, ar, apo) = a_h;
    *(uint4*)&SAl(0, ar, apo) = a_l;
    *(uint4*)&SBh(0, bp, bc4) = b_h;
    *(uint4*)&SBl(0, bp, bc4) = b_l;
    __syncthreads();

    int cur = 0;
    for (int kp0 = 0; kp0 < KPAIRS; kp0 += 8) {
        const bool more = (kp0 + 8 < KPAIRS);
        if (more) {
            a_h = *(const uint4*)(Ahb + kp0 + 8);
            a_l = *(const uint4*)(Alb + kp0 + 8);
            b_h = *(const uint4*)(Bhb + (size_t)(kp0 + 8) * N);
            b_l = *(const uint4*)(Blb + (size_t)(kp0 + 8) * N);
        }

        uint32_t ahi[2][4], alo[2][4];
#pragma unroll
        for (int mt = 0; mt < 2; mt++) {
            const int m0 = wm * 32 + mt * 16;
            ahi[mt][0] = SAh(cur, m0 + gid,     tig);
            ahi[mt][1] = SAh(cur, m0 + gid + 8, tig);
            ahi[mt][2] = SAh(cur, m0 + gid,     tig + 4);
            ahi[mt][3] = SAh(cur, m0 + gid + 8, tig + 4);
            alo[mt][0] = SAl(cur, m0 + gid,     tig);
            alo[mt][1] = SAl(cur, m0 + gid + 8, tig);
            alo[mt][2] = SAl(cur, m0 + gid,     tig + 4);
            alo[mt][3] = SAl(cur, m0 + gid + 8, tig + 4);
        }
#pragma unroll
        for (int nt = 0; nt < 8; nt++) {
            const int n0 = wn * 64 + nt * 8;
            uint32_t bh[2], bl[2];
            bh[0] = SBh(cur, tig,     n0 + gid);
            bh[1] = SBh(cur, tig + 4, n0 + gid);
            bl[0] = SBl(cur, tig,     n0 + gid);
            bl[1] = SBl(cur, tig + 4, n0 + gid);
#pragma unroll
            for (int mt = 0; mt < 2; mt++) {
                mma_bf16(c[mt][nt], ahi[mt], bh);
                mma_bf16(c[mt][nt], alo[mt], bh);
                mma_bf16(c[mt][nt], ahi[mt], bl);
            }
        }

        if (more) {
            const int nxt = cur ^ 1;
            *(uint4*)&SAh(nxt, ar, apo) = a_h;
            *(uint4*)&SAl(nxt, ar, apo) = a_l;
            *(uint4*)&SBh(nxt, bp, bc4) = b_h;
            *(uint4*)&SBl(nxt, bp, bc4) = b_l;
            __syncthreads();
            cur = nxt;
        }
    }

#pragma unroll
    for (int mt = 0; mt < 2; mt++) {
        const int m_lo = row0 + wm * 32 + mt * 16 + gid;
        const int m_hi = m_lo + 8;
#pragma unroll
        for (int nt = 0; nt < 8; nt++) {
            const int n = col0 + wn * 64 + nt * 8 + 2 * tig;
            const float b0 = bias[n], b1 = bias[n + 1];
            float v00 = c[mt][nt][0] + b0, v01 = c[mt][nt][1] + b1;
            float v10 = c[mt][nt][2] + b0, v11 = c[mt][nt][3] + b1;
            if (headsplit) {
                const int b_lo = m_lo / SEQ, s_lo = m_lo % SEQ;
                const int b_hi = m_hi / SEQ, s_hi = m_hi % SEQ;
                const int h = n / HDIM, d = n % HDIM;
                C[(((size_t)(b_lo*HEADS + h))*SEQ + s_lo)*HDIM + d    ] = v00;
                C[(((size_t)(b_lo*HEADS + h))*SEQ + s_lo)*HDIM + d + 1] = v01;
                C[(((size_t)(b_hi*HEADS + h))*SEQ + s_hi)*HDIM + d    ] = v10;
                C[(((size_t)(b_hi*HEADS + h))*SEQ + s_hi)*HDIM + d + 1] = v11;
            } else {
                C[(size_t)m_lo * N + n    ] = v00;
                C[(size_t)m_lo * N + n + 1] = v01;
                C[(size_t)m_hi * N + n    ] = v10;
                C[(size_t)m_hi * N + n + 1] = v11;
            }
        }
    }
}

// merged Q/K/V projections: blockIdx.z selects weight plane/bias/output
__global__ __launch_bounds__(256)
void gemm_proj(const uint32_t* __restrict__ Ah, const uint32_t* __restrict__ Al,
               const uint32_t* __restrict__ Wh, const uint32_t* __restrict__ Wl,
               const float* __restrict__ b0, const float* __restrict__ b1,
               const float* __restrict__ b2,
               float* __restrict__ C0, float* __restrict__ C1, float* __restrict__ C2)
{
    extern __shared__ __align__(16) uint32_t smu[];
    const int z = blockIdx.z;
    const float* b = (z == 0) ? b0 : (z == 1) ? b1 : b2;
    float*       C = (z == 0) ? C0 : (z == 1) ? C1 : C2;
    gemm_body(Ah, Al, Wh + (size_t)z * KPAIRS * EMB, Wl + (size_t)z * KPAIRS * EMB,
              b, C, 1, smu);
}

__global__ __launch_bounds__(256)
void gemm_out(const uint32_t* __restrict__ Ah, const uint32_t* __restrict__ Al,
              const uint32_t* __restrict__ Wh, const uint32_t* __restrict__ Wl,
              const float* __restrict__ b, float* __restrict__ C)
{
    extern __shared__ __align__(16) uint32_t smu[];
    gemm_body(Ah, Al, Wh + (size_t)3 * KPAIRS * EMB, Wl + (size_t)3 * KPAIRS * EMB,
              b, C, 0, smu);
}

// ---------------------------------------------------------------------------
// Causal flash attention (R12 structure), single-pass TF32, exp2 softmax.
// Block: 128 q-rows, 128 threads, 4 warps; warp owns 32 rows (2 m-tiles).
// ---------------------------------------------------------------------------
#define QS(r,c)    sQ[(r)*68 + (c)]
#define KS_(r,c)   sK[(r)*68 + (c)]
#define VS_(r,c)   sV[(r)*72 + (c)]
#define SSW(cc,rr) sP[(cc)*40 + (rr)]

#define ATTN_SMEM_FLOATS (128*68 + 32*68 + 32*72 + 4*32*40)
#define QSCALE (0.125f * 1.44269504088896340736f)   // 1/sqrt(D) * log2(e)

__global__ __launch_bounds__(128)
void attn_tf32(const float* __restrict__ Q, const float* __restrict__ Kg,
               const float* __restrict__ Vg, float* __restrict__ O)
{
    extern __shared__ __align__(16) float smem[];
    float* sQ  = smem;                 // 128 x 68
    float* sK  = sQ + 128*68;          // 32 x 68
    float* sV  = sK + 32*68;           // 32 x 72
    float* sPb = sV + 32*72;           // 4 warps x (32 cols x 40)

    const int bh  = blockIdx.y;
    const int qt  = blockIdx.x;
    const int tid = threadIdx.x;
    const int wid = tid >> 5;
    const int lane = tid & 31;
    const int gid = lane >> 2;
    const int tig = lane & 3;
    const int m0  = wid * 32;
    float* sP = sPb + wid * (32*40);

    const float* Qbase = Q + ((size_t)bh * SEQ + qt * 128) * HDIM;
    const float* Kbase = Kg + (size_t)bh * SEQ * HDIM;
    const float* Vbase = Vg + (size_t)bh * SEQ * HDIM;

    // stage Q (128x64), scaled by 1/sqrt(D)*log2e, cvt to tf32
    {
        const float* qr = Qbase + (size_t)tid * HDIM;
#pragma unroll
        for (int i = 0; i < 16; i++) {
            float4 v = *(const float4*)(qr + i * 4);
            v.x *= QSCALE; v.y *= QSCALE; v.z *= QSCALE; v.w *= QSCALE;
            *(float4*)&QS(tid, i * 4) = cvt4(v);
        }
    }
    __syncthreads();

    float o[2][8][4];
#pragma unroll
    for (int mt = 0; mt < 2; mt++)
#pragma unroll
        for (int nt = 0; nt < 8; nt++)
#pragma unroll
            for (int i = 0; i < 4; i++) o[mt][nt][i] = 0.f;
    float mrow[2][2] = {{-INFINITY,-INFINITY},{-INFINITY,-INFINITY}};
    float lrow[2][2] = {{0.f,0.f},{0.f,0.f}};

    const int qmax_warp = qt * 128 + m0 + 31;
    const int nch = 4 * qt + 4;

    for (int ch = 0; ch < nch; ch++) {
        // stage K,V chunk (32x64), cvt to tf32
        {
            const int kr = tid >> 2, kc = (tid & 3) * 16;
            const float* kp = Kbase + (size_t)(ch * 32 + kr) * HDIM + kc;
            const float* vp = Vbase + (size_t)(ch * 32 + kr) * HDIM + kc;
#pragma unroll
            for (int i = 0; i < 4; i++) {
                *(float4*)&KS_(kr, kc + i * 4) = cvt4(*(const float4*)(kp + i * 4));
                *(float4*)&VS_(kr, kc + i * 4) = cvt4(*(const float4*)(vp + i * 4));
            }
        }
        __syncthreads();

        if (ch * 32 <= qmax_warp) {
            // ---- S = Q K^T : 32 rows x 32 keys per warp ----
            float s[2][4][4];
#pragma unroll
            for (int mt = 0; mt < 2; mt++)
#pragma unroll
                for (int nt = 0; nt < 4; nt++)
#pragma unroll
                    for (int i = 0; i < 4; i++) s[mt][nt][i] = 0.f;

#pragma unroll
            for (int ks = 0; ks < 8; ks++) {
                uint32_t a[2][4];
#pragma unroll
                for (int mt = 0; mt < 2; mt++) {
                    const int r0 = m0 + mt * 16;
                    a[mt][0] = __float_as_uint(QS(r0 + gid,     ks*8 + tig));
                    a[mt][1] = __float_as_uint(QS(r0 + gid + 8, ks*8 + tig));
                    a[mt][2] = __float_as_uint(QS(r0 + gid,     ks*8 + tig + 4));
                    a[mt][3] = __float_as_uint(QS(r0 + gid + 8, ks*8 + tig + 4));
                }
#pragma unroll
                for (int nt = 0; nt < 4; nt++) {
                    uint32_t b[2];
                    b[0] = __float_as_uint(KS_(nt*8 + gid, ks*8 + tig));
                    b[1] = __float_as_uint(KS_(nt*8 + gid, ks*8 + tig + 4));
                    mma_tf32(s[0][nt], a[0], b);
                    mma_tf32(s[1][nt], a[1], b);
                }
            }

            // ---- register online softmax (log2 domain) ----
#pragma unroll
            for (int mt = 0; mt < 2; mt++) {
#pragma unroll
                for (int half = 0; half < 2; half++) {
                    const int qrow = qt * 128 + m0 + mt * 16 + gid + half * 8;
                    const int cb   = ch * 32 + 2 * tig;
                    float mx = -INFINITY;
#pragma unroll
                    for (int nt = 0; nt < 4; nt++) {
#pragma unroll
                        for (int ii = 0; ii < 2; ii++) {
                            const int cc = cb + nt * 8 + ii;
                            if (cc <= qrow)
                                mx = fmaxf(mx, s[mt][nt][half * 2 + ii]);
                        }
                    }
                    mx = fmaxf(mx, __shfl_xor_sync(0xffffffffu, mx, 1));
                    mx = fmaxf(mx, __shfl_xor_sync(0xffffffffu, mx, 2));
                    const float mold = mrow[mt][half];
                    const float mnew = fmaxf(mold, mx);
                    const float msafe = (mnew == -INFINITY) ? 0.f : mnew;
                    const float corr  = (mold == -INFINITY) ? 0.f : exp2f(mold - msafe);
                    float sum = 0.f;
#pragma unroll
                    for (int nt = 0; nt < 4; nt++) {
#pragma unroll
                        for (int ii = 0; ii < 2; ii++) {
                            const int cc = cb + nt * 8 + ii;
                            float p = (cc <= qrow) ? exp2f(s[mt][nt][half*2+ii] - msafe) : 0.f;
                            s[mt][nt][half*2+ii] = p;
                            sum += p;
                        }
                    }
                    sum += __shfl_xor_sync(0xffffffffu, sum, 1);
                    sum += __shfl_xor_sync(0xffffffffu, sum, 2);
                    lrow[mt][half] = lrow[mt][half] * corr + sum;
                    mrow[mt][half] = mnew;
#pragma unroll
                    for (int nt = 0; nt < 8; nt++) {
                        o[mt][nt][half*2+0] *= corr;
                        o[mt][nt][half*2+1] *= corr;
                    }
                }
            }

            // ---- write P (tf32-cvt'd) to per-warp buffer [col][row] stride 40 ----
#pragma unroll
            for (int mt = 0; mt < 2; mt++) {
                const int rl = mt * 16 + gid;
#pragma unroll
                for (int nt = 0; nt < 4; nt++) {
                    const int cc = nt * 8 + 2 * tig;
                    SSW(cc,     rl)     = __uint_as_float(tf32_rna(s[mt][nt][0]));
                    SSW(cc + 1, rl)     = __uint_as_float(tf32_rna(s[mt][nt][1]));
                    SSW(cc,     rl + 8) = __uint_as_float(tf32_rna(s[mt][nt][2]));
                    SSW(cc + 1, rl + 8) = __uint_as_float(tf32_rna(s[mt][nt][3]));
                }
            }
            __syncwarp();

            // ---- O += P V ----
#pragma unroll
            for (int ks = 0; ks < 4; ks++) {
                uint32_t p[2][4];
#pragma unroll
                for (int mt = 0; mt < 2; mt++) {
                    const int rl = mt * 16 + gid;
                    p[mt][0] = __float_as_uint(SSW(ks*8 + tig,     rl));
                    p[mt][1] = __float_as_uint(SSW(ks*8 + tig,     rl + 8));
                    p[mt][2] = __float_as_uint(SSW(ks*8 + tig + 4, rl));
                    p[mt][3] = __float_as_uint(SSW(ks*8 + tig + 4, rl + 8));
                }
#pragma unroll
                for (int nt = 0; nt < 8; nt++) {
                    uint32_t v[2];
                    v[0] = __float_as_uint(VS_(ks*8 + tig,     nt*8 + gid));
                    v[1] = __float_as_uint(VS_(ks*8 + tig + 4, nt*8 + gid));
                    mma_tf32(o[0][nt], p[0], v);
                    mma_tf32(o[1][nt], p[1], v);
                }
            }
        }
        __syncthreads();
    }

    // epilogue: normalize and store to [b][s][h*64+d]
    const int b = bh / HEADS, h = bh % HEADS;
#pragma unroll
    for (int mt = 0; mt < 2; mt++) {
#pragma unroll
        for (int half = 0; half < 2; half++) {
            const float inv = 1.f / lrow[mt][half];
            const int sg = qt * 128 + m0 + mt * 16 + gid + half * 8;
            float* orow = O + ((size_t)(b * SEQ + sg)) * EMB + h * HDIM;
#pragma unroll
            for (int nt = 0; nt < 8; nt++) {
                const int cc = nt * 8 + 2 * tig;
                orow[cc]     = o[mt][nt][half*2+0] * inv;
                orow[cc + 1] = o[mt][nt][half*2+1] * inv;
            }
        }
    }
}

// ---------------------------------------------------------------------------
extern "C" void kernel_launch(void* const* d_in, const int* in_sizes, int n_in,
                              void* d_out, int out_size)
{
    const float* x  = (const float*)d_in[0];
    const float* Wq = (const float*)d_in[1];
    const float* bq = (const float*)d_in[2];
    const float* Wk = (const float*)d_in[3];
    const float* bk = (const float*)d_in[4];
    const float* Wv = (const float*)d_in[5];
    const float* bv = (const float*)d_in[6];
    const float* Wo = (const float*)d_in[7];
    const float* bo = (const float*)d_in[8];
    float* out = (float*)d_out;

    float *q_ptr, *k_ptr, *v_ptr, *ao_ptr;
    uint32_t *xh, *xl, *aoh, *aol, *wh, *wl;
    cudaGetSymbolAddress((void**)&q_ptr,  g_q);
    cudaGetSymbolAddress((void**)&k_ptr,  g_k);
    cudaGetSymbolAddress((void**)&v_ptr,  g_v);
    cudaGetSymbolAddress((void**)&ao_ptr, g_ao);
    cudaGetSymbolAddress((void**)&xh,  g_xh);
    cudaGetSymbolAddress((void**)&xl,  g_xl);
    cudaGetSymbolAddress((void**)&aoh, g_aoh);
    cudaGetSymbolAddress((void**)&aol, g_aol);
    cudaGetSymbolAddress((void**)&wh,  g_wh);
    cudaGetSymbolAddress((void**)&wl,  g_wl);

    const int attn_smem = ATTN_SMEM_FLOATS * 4;
    static int attr_set = 0;
    if (!attr_set) {
        cudaFuncSetAttribute(attn_tf32,  cudaFuncAttributeMaxDynamicSharedMemorySize, attn_smem);
        cudaFuncSetAttribute(gemm_proj,  cudaFuncAttributeMaxDynamicSharedMemorySize, GEMM_SMEM_BYTES);
        cudaFuncSetAttribute(gemm_out,   cudaFuncAttributeMaxDynamicSharedMemorySize, GEMM_SMEM_BYTES);
        attr_set = 1;
    }

    // pre-split x and weights
    {
        const int npairs = MROWS * KPAIRS;                 // 4.19M
        split_pairs<<<(npairs + 255) / 256, 256>>>(x, xh, xl, npairs);
        dim3 wgrid((KPAIRS * EMB) / 256, 4);               // (2048, 4)
        split_w<<<wgrid, 256>>>(Wq, Wk, Wv, Wo, wh, wl);
    }

    dim3 gblk(256);
    dim3 pgrid(EMB / 128, MROWS / 128, 3);   // (8, 64, 3)
    gemm_proj<<<pgrid, gblk, GEMM_SMEM_BYTES>>>(xh, xl, wh, wl, bq, bk, bv,
                                                q_ptr, k_ptr, v_ptr);

    dim3 agrid(SEQ / 128, BATCH * HEADS);    // (16, 64)
    attn_tf32<<<agrid, 128, attn_smem>>>(q_ptr, k_ptr, v_ptr, ao_ptr);

    {
        const int npairs = MROWS * KPAIRS;
        split_pairs<<<(npairs + 255) / 256, 256>>>(ao_ptr, aoh, aol, npairs);
    }

    dim3 ogrid(EMB / 128, MROWS / 128, 1);   // (8, 64)
    gemm_out<<<ogrid, gblk, GEMM_SMEM_BYTES>>>(aoh, aol, wh, wl, bo, out);
}

// round 15
// speedup vs baseline: 1.1253x; 1.0083x over previous
#include <cuda_runtime.h>
#include <cuda_bf16.h>
#include <cstdint>
#include <cmath>

#define BATCH 4
#define SEQ   2048
#define EMB   1024
#define HEADS 16
#define HDIM  64
#define MROWS (BATCH*SEQ)   // 8192
#define KPAIRS (EMB/2)      // 512

// Scratch (no allocations allowed)
__device__ float g_q[BATCH*HEADS*SEQ*HDIM];
__device__ float g_k[BATCH*HEADS*SEQ*HDIM];
__device__ float g_v[BATCH*HEADS*SEQ*HDIM];
// pre-split bf16 hi/lo planes (packed pairs as u32)
__device__ uint32_t g_xh[MROWS*KPAIRS],  g_xl[MROWS*KPAIRS];    // x   [m][k/2]
__device__ uint32_t g_aoh[MROWS*KPAIRS], g_aol[MROWS*KPAIRS];   // ao  [m][k/2]
__device__ uint32_t g_wh[4*KPAIRS*EMB],  g_wl[4*KPAIRS*EMB];    // W   [k/2][n] x4

// ---------------------------------------------------------------------------
// helpers
// ---------------------------------------------------------------------------
__device__ __forceinline__ uint32_t tf32_rna(float x) {
    uint32_t r;
    asm("cvt.rna.tf32.f32 %0, %1;" : "=r"(r) : "f"(x));
    return r;
}
__device__ __forceinline__ float4 cvt4(float4 v) {
    v.x = __uint_as_float(tf32_rna(v.x));
    v.y = __uint_as_float(tf32_rna(v.y));
    v.z = __uint_as_float(tf32_rna(v.z));
    v.w = __uint_as_float(tf32_rna(v.w));
    return v;
}
__device__ __forceinline__ void mma_tf32(float* c, const uint32_t* a, const uint32_t* b) {
    asm volatile(
        "mma.sync.aligned.m16n8k8.row.col.f32.tf32.tf32.f32 "
        "{%0,%1,%2,%3}, {%4,%5,%6,%7}, {%8,%9}, {%0,%1,%2,%3};"
        : "+f"(c[0]), "+f"(c[1]), "+f"(c[2]), "+f"(c[3])
        : "r"(a[0]), "r"(a[1]), "r"(a[2]), "r"(a[3]), "r"(b[0]), "r"(b[1]));
}
__device__ __forceinline__ void mma_bf16(float* c, const uint32_t* a, const uint32_t* b) {
    asm volatile(
        "mma.sync.aligned.m16n8k16.row.col.f32.bf16.bf16.f32 "
        "{%0,%1,%2,%3}, {%4,%5,%6,%7}, {%8,%9}, {%0,%1,%2,%3};"
        : "+f"(c[0]), "+f"(c[1]), "+f"(c[2]), "+f"(c[3])
        : "r"(a[0]), "r"(a[1]), "r"(a[2]), "r"(a[3]), "r"(b[0]), "r"(b[1]));
}
__device__ __forceinline__ void bf16split2(float x0, float x1, uint32_t& hi, uint32_t& lo) {
    __nv_bfloat16 h0 = __float2bfloat16_rn(x0);
    __nv_bfloat16 h1 = __float2bfloat16_rn(x1);
    float r0 = x0 - __bfloat162float(h0);
    float r1 = x1 - __bfloat162float(h1);
    __nv_bfloat16 l0 = __float2bfloat16_rn(r0);
    __nv_bfloat16 l1 = __float2bfloat16_rn(r1);
    hi = ((uint32_t)__bfloat16_as_ushort(h1) << 16) | (uint32_t)__bfloat16_as_ushort(h0);
    lo = ((uint32_t)__bfloat16_as_ushort(l1) << 16) | (uint32_t)__bfloat16_as_ushort(l0);
}

// ---------------------------------------------------------------------------
// pre-split kernels
// ---------------------------------------------------------------------------
__global__ __launch_bounds__(256)
void split_pairs(const float* __restrict__ src, uint32_t* __restrict__ hp,
                 uint32_t* __restrict__ lp, int n_pairs)
{
    int i = blockIdx.x * blockDim.x + threadIdx.x;
    if (i >= n_pairs) return;
    const float2 v = ((const float2*)src)[i];
    uint32_t h, l;
    bf16split2(v.x, v.y, h, l);
    hp[i] = h; lp[i] = l;
}

__global__ __launch_bounds__(256)
void split_w(const float* __restrict__ W0, const float* __restrict__ W1,
             const float* __restrict__ W2, const float* __restrict__ W3,
             uint32_t* __restrict__ hp, uint32_t* __restrict__ lp)
{
    const int z = blockIdx.y;
    const float* W = (z == 0) ? W0 : (z == 1) ? W1 : (z == 2) ? W2 : W3;
    int i = blockIdx.x * blockDim.x + threadIdx.x;
    const int kp = i >> 10, n = i & (EMB - 1);
    const float a = W[((size_t)(2*kp))   * EMB + n];
    const float b = W[((size_t)(2*kp+1)) * EMB + n];
    uint32_t h, l;
    bf16split2(a, b, h, l);
    hp[(size_t)z * KPAIRS * EMB + i] = h;
    lp[(size_t)z * KPAIRS * EMB + i] = l;
}

// ---------------------------------------------------------------------------
// 3xBF16 GEMM body reading pre-split planes. Tile 128x128x16, 256 thr, 8 warps.
// ---------------------------------------------------------------------------
#define GSTG 5248
#define SAh(st,r,p) smu[(st)*GSTG          + (r)*12  + (p)]
#define SAl(st,r,p) smu[(st)*GSTG + 1536   + (r)*12  + (p)]
#define SBh(st,p,c) smu[(st)*GSTG + 3072   + (p)*136 + (c)]
#define SBl(st,p,c) smu[(st)*GSTG + 4160   + (p)*136 + (c)]
#define GEMM_SMEM_BYTES (2*GSTG*4)

__device__ __forceinline__ void gemm_body(
    const uint32_t* __restrict__ Ah, const uint32_t* __restrict__ Al,
    const uint32_t* __restrict__ Bh, const uint32_t* __restrict__ Bl,
    const float* __restrict__ bias, float* __restrict__ C,
    int headsplit, uint32_t* smu)
{
    const int N = EMB;
    const int tid  = threadIdx.x;
    const int wid  = tid >> 5;
    const int lane = tid & 31;
    const int gid  = lane >> 2;
    const int tig  = lane & 3;
    const int wm   = wid >> 1;
    const int wn   = wid & 1;
    const int row0 = blockIdx.y * 128;
    const int col0 = blockIdx.x * 128;

    float c[2][8][4];
#pragma unroll
    for (int mt = 0; mt < 2; mt++)
#pragma unroll
        for (int nt = 0; nt < 8; nt++)
#pragma unroll
            for (int i = 0; i < 4; i++) c[mt][nt][i] = 0.f;

    const int ar = tid >> 1, apo = (tid & 1) * 4;
    const int bp = tid >> 5, bc4 = (tid & 31) * 4;

    const uint32_t* Ahb = Ah + (size_t)(row0 + ar) * KPAIRS + apo;
    const uint32_t* Alb = Al + (size_t)(row0 + ar) * KPAIRS + apo;
    const uint32_t* Bhb = Bh + (size_t)bp * N + col0 + bc4;
    const uint32_t* Blb = Bl + (size_t)bp * N + col0 + bc4;

    uint4 a_h = *(const uint4*)(Ahb);
    uint4 a_l = *(const uint4*)(Alb);
    uint4 b_h = *(const uint4*)(Bhb);
    uint4 b_l = *(const uint4*)(Blb);

    *(uint4*)&SAh(0, ar, apo) = a_h;
    *(uint4*)&SAl(0, ar, apo) = a_l;
    *(uint4*)&SBh(0, bp, bc4) = b_h;
    *(uint4*)&SBl(0, bp, bc4) = b_l;
    __syncthreads();

    int cur = 0;
    for (int kp0 = 0; kp0 < KPAIRS; kp0 += 8) {
        const bool more = (kp0 + 8 < KPAIRS);
        if (more) {
            a_h = *(const uint4*)(Ahb + kp0 + 8);
            a_l = *(const uint4*)(Alb + kp0 + 8);
            b_h = *(const uint4*)(Bhb + (size_t)(kp0 + 8) * N);
            b_l = *(const uint4*)(Blb + (size_t)(kp0 + 8) * N);
        }

        uint32_t ahi[2][4], alo[2][4];
#pragma unroll
        for (int mt = 0; mt < 2; mt++) {
            const int m0 = wm * 32 + mt * 16;
            ahi[mt][0] = SAh(cur, m0 + gid,     tig);
            ahi[mt][1] = SAh(cur, m0 + gid + 8, tig);
            ahi[mt][2] = SAh(cur, m0 + gid,     tig + 4);
            ahi[mt][3] = SAh(cur, m0 + gid + 8, tig + 4);
            alo[mt][0] = SAl(cur, m0 + gid,     tig);
            alo[mt][1] = SAl(cur, m0 + gid + 8, tig);
            alo[mt][2] = SAl(cur, m0 + gid,     tig + 4);
            alo[mt][3] = SAl(cur, m0 + gid + 8, tig + 4);
        }
#pragma unroll
        for (int nt = 0; nt < 8; nt++) {
            const int n0 = wn * 64 + nt * 8;
            uint32_t bh[2], bl[2];
            bh[0] = SBh(cur, tig,     n0 + gid);
            bh[1] = SBh(cur, tig + 4, n0 + gid);
            bl[0] = SBl(cur, tig,     n0 + gid);
            bl[1] = SBl(cur, tig + 4, n0 + gid);
#pragma unroll
            for (int mt = 0; mt < 2; mt++) {
                mma_bf16(c[mt][nt], ahi[mt], bh);
                mma_bf16(c[mt][nt], alo[mt], bh);
                mma_bf16(c[mt][nt], ahi[mt], bl);
            }
        }

        if (more) {
            const int nxt = cur ^ 1;
            *(uint4*)&SAh(nxt, ar, apo) = a_h;
            *(uint4*)&SAl(nxt, ar, apo) = a_l;
            *(uint4*)&SBh(nxt, bp, bc4) = b_h;
            *(uint4*)&SBl(nxt, bp, bc4) = b_l;
            __syncthreads();
            cur = nxt;
        }
    }

#pragma unroll
    for (int mt = 0; mt < 2; mt++) {
        const int m_lo = row0 + wm * 32 + mt * 16 + gid;
        const int m_hi = m_lo + 8;
#pragma unroll
        for (int nt = 0; nt < 8; nt++) {
            const int n = col0 + wn * 64 + nt * 8 + 2 * tig;
            const float b0 = bias[n], b1 = bias[n + 1];
            float v00 = c[mt][nt][0] + b0, v01 = c[mt][nt][1] + b1;
            float v10 = c[mt][nt][2] + b0, v11 = c[mt][nt][3] + b1;
            if (headsplit) {
                const int b_lo = m_lo / SEQ, s_lo = m_lo % SEQ;
                const int b_hi = m_hi / SEQ, s_hi = m_hi % SEQ;
                const int h = n / HDIM, d = n % HDIM;
                C[(((size_t)(b_lo*HEADS + h))*SEQ + s_lo)*HDIM + d    ] = v00;
                C[(((size_t)(b_lo*HEADS + h))*SEQ + s_lo)*HDIM + d + 1] = v01;
                C[(((size_t)(b_hi*HEADS + h))*SEQ + s_hi)*HDIM + d    ] = v10;
                C[(((size_t)(b_hi*HEADS + h))*SEQ + s_hi)*HDIM + d + 1] = v11;
            } else {
                C[(size_t)m_lo * N + n    ] = v00;
                C[(size_t)m_lo * N + n + 1] = v01;
                C[(size_t)m_hi * N + n    ] = v10;
                C[(size_t)m_hi * N + n + 1] = v11;
            }
        }
    }
}

__global__ __launch_bounds__(256)
void gemm_proj(const uint32_t* __restrict__ Ah, const uint32_t* __restrict__ Al,
               const uint32_t* __restrict__ Wh, const uint32_t* __restrict__ Wl,
               const float* __restrict__ b0, const float* __restrict__ b1,
               const float* __restrict__ b2,
               float* __restrict__ C0, float* __restrict__ C1, float* __restrict__ C2)
{
    extern __shared__ __align__(16) uint32_t smu[];
    const int z = blockIdx.z;
    const float* b = (z == 0) ? b0 : (z == 1) ? b1 : b2;
    float*       C = (z == 0) ? C0 : (z == 1) ? C1 : C2;
    gemm_body(Ah, Al, Wh + (size_t)z * KPAIRS * EMB, Wl + (size_t)z * KPAIRS * EMB,
              b, C, 1, smu);
}

__global__ __launch_bounds__(256)
void gemm_out(const uint32_t* __restrict__ Ah, const uint32_t* __restrict__ Al,
              const uint32_t* __restrict__ Wh, const uint32_t* __restrict__ Wl,
              const float* __restrict__ b, float* __restrict__ C)
{
    extern __shared__ __align__(16) uint32_t smu[];
    gemm_body(Ah, Al, Wh + (size_t)3 * KPAIRS * EMB, Wl + (size_t)3 * KPAIRS * EMB,
              b, C, 0, smu);
}

// ---------------------------------------------------------------------------
// Causal flash attention v5: single-pass TF32, exp2 softmax, Q frags in regs,
// work-descending block order, mask fast-path, fused ao bf16-split epilogue.
// Block: 128 q-rows, 128 threads, 4 warps; warp owns 32 rows (2 m-tiles).
// ---------------------------------------------------------------------------
#define QS(r,c)    sQ[(r)*68 + (c)]
#define KS_(r,c)   sK[(r)*68 + (c)]
#define VS_(r,c)   sV[(r)*72 + (c)]
#define SSW(cc,rr) sP[(cc)*40 + (rr)]

#define ATTN_SMEM_FLOATS (128*68 + 32*68 + 32*72 + 4*32*40)
#define QSCALE (0.125f * 1.44269504088896340736f)   // 1/sqrt(D) * log2(e)

__global__ __launch_bounds__(128)
void attn_tf32(const float* __restrict__ Q, const float* __restrict__ Kg,
               const float* __restrict__ Vg,
               uint32_t* __restrict__ AOh, uint32_t* __restrict__ AOl)
{
    extern __shared__ __align__(16) float smem[];
    float* sQ  = smem;                 // 128 x 68
    float* sK  = sQ + 128*68;          // 32 x 68
    float* sV  = sK + 32*68;           // 32 x 72
    float* sPb = sV + 32*72;           // 4 warps x (32 cols x 40)

    const int bh  = blockIdx.y;
    const int qt  = (gridDim.x - 1) - blockIdx.x;   // big-work blocks first
    const int tid = threadIdx.x;
    const int wid = tid >> 5;
    const int lane = tid & 31;
    const int gid = lane >> 2;
    const int tig = lane & 3;
    const int m0  = wid * 32;
    float* sP = sPb + wid * (32*40);

    const float* Qbase = Q + ((size_t)bh * SEQ + qt * 128) * HDIM;
    const float* Kbase = Kg + (size_t)bh * SEQ * HDIM;
    const float* Vbase = Vg + (size_t)bh * SEQ * HDIM;

    // stage Q (128x64), scaled by 1/sqrt(D)*log2e, cvt to tf32
    {
        const float* qr = Qbase + (size_t)tid * HDIM;
#pragma unroll
        for (int i = 0; i < 16; i++) {
            float4 v = *(const float4*)(qr + i * 4);
            v.x *= QSCALE; v.y *= QSCALE; v.z *= QSCALE; v.w *= QSCALE;
            *(float4*)&QS(tid, i * 4) = cvt4(v);
        }
    }
    __syncthreads();

    // Q fragments held in registers for the whole kernel
    uint32_t qa[2][8][4];
#pragma unroll
    for (int ks = 0; ks < 8; ks++) {
#pragma unroll
        for (int mt = 0; mt < 2; mt++) {
            const int r0 = m0 + mt * 16;
            qa[mt][ks][0] = __float_as_uint(QS(r0 + gid,     ks*8 + tig));
            qa[mt][ks][1] = __float_as_uint(QS(r0 + gid + 8, ks*8 + tig));
            qa[mt][ks][2] = __float_as_uint(QS(r0 + gid,     ks*8 + tig + 4));
            qa[mt][ks][3] = __float_as_uint(QS(r0 + gid + 8, ks*8 + tig + 4));
        }
    }

    float o[2][8][4];
#pragma unroll
    for (int mt = 0; mt < 2; mt++)
#pragma unroll
        for (int nt = 0; nt < 8; nt++)
#pragma unroll
            for (int i = 0; i < 4; i++) o[mt][nt][i] = 0.f;
    float mrow[2][2] = {{-INFINITY,-INFINITY},{-INFINITY,-INFINITY}};
    float lrow[2][2] = {{0.f,0.f},{0.f,0.f}};

    const int qmax_warp = qt * 128 + m0 + 31;
    const int qmin_warp = qt * 128 + m0;
    const int nch = 4 * qt + 4;

    for (int ch = 0; ch < nch; ch++) {
        // stage K,V chunk (32x64), cvt to tf32
        {
            const int kr = tid >> 2, kc = (tid & 3) * 16;
            const float* kp = Kbase + (size_t)(ch * 32 + kr) * HDIM + kc;
            const float* vp = Vbase + (size_t)(ch * 32 + kr) * HDIM + kc;
#pragma unroll
            for (int i = 0; i < 4; i++) {
                *(float4*)&KS_(kr, kc + i * 4) = cvt4(*(const float4*)(kp + i * 4));
                *(float4*)&VS_(kr, kc + i * 4) = cvt4(*(const float4*)(vp + i * 4));
            }
        }
        __syncthreads();

        if (ch * 32 <= qmax_warp) {
            const bool needmask = (ch * 32 + 31 > qmin_warp);

            // ---- S = Q K^T : 32 rows x 32 keys per warp ----
            float s[2][4][4];
#pragma unroll
            for (int mt = 0; mt < 2; mt++)
#pragma unroll
                for (int nt = 0; nt < 4; nt++)
#pragma unroll
                    for (int i = 0; i < 4; i++) s[mt][nt][i] = 0.f;

#pragma unroll
            for (int ks = 0; ks < 8; ks++) {
#pragma unroll
                for (int nt = 0; nt < 4; nt++) {
                    uint32_t b[2];
                    b[0] = __float_as_uint(KS_(nt*8 + gid, ks*8 + tig));
                    b[1] = __float_as_uint(KS_(nt*8 + gid, ks*8 + tig + 4));
                    mma_tf32(s[0][nt], qa[0][ks], b);
                    mma_tf32(s[1][nt], qa[1][ks], b);
                }
            }

            // ---- register online softmax (log2 domain) ----
#pragma unroll
            for (int mt = 0; mt < 2; mt++) {
#pragma unroll
                for (int half = 0; half < 2; half++) {
                    const int qrow = qt * 128 + m0 + mt * 16 + gid + half * 8;
                    const int cb   = ch * 32 + 2 * tig;
                    float mx = -INFINITY;
                    if (needmask) {
#pragma unroll
                        for (int nt = 0; nt < 4; nt++)
#pragma unroll
                            for (int ii = 0; ii < 2; ii++) {
                                const int cc = cb + nt * 8 + ii;
                                if (cc <= qrow)
                                    mx = fmaxf(mx, s[mt][nt][half * 2 + ii]);
                            }
                    } else {
#pragma unroll
                        for (int nt = 0; nt < 4; nt++)
#pragma unroll
                            for (int ii = 0; ii < 2; ii++)
                                mx = fmaxf(mx, s[mt][nt][half * 2 + ii]);
                    }
                    mx = fmaxf(mx, __shfl_xor_sync(0xffffffffu, mx, 1));
                    mx = fmaxf(mx, __shfl_xor_sync(0xffffffffu, mx, 2));
                    const float mold = mrow[mt][half];
                    const float mnew = fmaxf(mold, mx);
                    const float msafe = (mnew == -INFINITY) ? 0.f : mnew;
                    const float corr  = (mold == -INFINITY) ? 0.f : exp2f(mold - msafe);
                    float sum = 0.f;
                    if (needmask) {
#pragma unroll
                        for (int nt = 0; nt < 4; nt++)
#pragma unroll
                            for (int ii = 0; ii < 2; ii++) {
                                const int cc = cb + nt * 8 + ii;
                                float p = (cc <= qrow) ? exp2f(s[mt][nt][half*2+ii] - msafe) : 0.f;
                                s[mt][nt][half*2+ii] = p;
                                sum += p;
                            }
                    } else {
#pragma unroll
                        for (int nt = 0; nt < 4; nt++)
#pragma unroll
                            for (int ii = 0; ii < 2; ii++) {
                                float p = exp2f(s[mt][nt][half*2+ii] - msafe);
                                s[mt][nt][half*2+ii] = p;
                                sum += p;
                            }
                    }
                    sum += __shfl_xor_sync(0xffffffffu, sum, 1);
                    sum += __shfl_xor_sync(0xffffffffu, sum, 2);
                    lrow[mt][half] = lrow[mt][half] * corr + sum;
                    mrow[mt][half] = mnew;
#pragma unroll
                    for (int nt = 0; nt < 8; nt++) {
                        o[mt][nt][half*2+0] *= corr;
                        o[mt][nt][half*2+1] *= corr;
                    }
                }
            }

            // ---- write P (tf32-cvt'd) to per-warp buffer [col][row] stride 40 ----
#pragma unroll
            for (int mt = 0; mt < 2; mt++) {
                const int rl = mt * 16 + gid;
#pragma unroll
                for (int nt = 0; nt < 4; nt++) {
                    const int cc = nt * 8 + 2 * tig;
                    SSW(cc,     rl)     = __uint_as_float(tf32_rna(s[mt][nt][0]));
                    SSW(cc + 1, rl)     = __uint_as_float(tf32_rna(s[mt][nt][1]));
                    SSW(cc,     rl + 8) = __uint_as_float(tf32_rna(s[mt][nt][2]));
                    SSW(cc + 1, rl + 8) = __uint_as_float(tf32_rna(s[mt][nt][3]));
                }
            }
            __syncwarp();

            // ---- O += P V ----
#pragma unroll
            for (int ks = 0; ks < 4; ks++) {
                uint32_t p[2][4];
#pragma unroll
                for (int mt = 0; mt < 2; mt++) {
                    const int rl = mt * 16 + gid;
                    p[mt][0] = __float_as_uint(SSW(ks*8 + tig,     rl));
                    p[mt][1] = __float_as_uint(SSW(ks*8 + tig,     rl + 8));
                    p[mt][2] = __float_as_uint(SSW(ks*8 + tig + 4, rl));
                    p[mt][3] = __float_as_uint(SSW(ks*8 + tig + 4, rl + 8));
                }
#pragma unroll
                for (int nt = 0; nt < 8; nt++) {
                    uint32_t v[2];
                    v[0] = __float_as_uint(VS_(ks*8 + tig,     nt*8 + gid));
                    v[1] = __float_as_uint(VS_(ks*8 + tig + 4, nt*8 + gid));
                    mma_tf32(o[0][nt], p[0], v);
                    mma_tf32(o[1][nt], p[1], v);
                }
            }
        }
        __syncthreads();
    }

    // epilogue: normalize and write bf16 hi/lo planes directly
    const int b = bh / HEADS, h = bh % HEADS;
#pragma unroll
    for (int mt = 0; mt < 2; mt++) {
#pragma unroll
        for (int half = 0; half < 2; half++) {
            const float inv = 1.f / lrow[mt][half];
            const int sg = qt * 128 + m0 + mt * 16 + gid + half * 8;
            const size_t rowbase = (size_t)(b * SEQ + sg) * KPAIRS + h * (HDIM/2);
#pragma unroll
            for (int nt = 0; nt < 8; nt++) {
                const int cc = nt * 8 + 2 * tig;
                uint32_t hi, lo;
                bf16split2(o[mt][nt][half*2+0] * inv, o[mt][nt][half*2+1] * inv, hi, lo);
                AOh[rowbase + (cc >> 1)] = hi;
                AOl[rowbase + (cc >> 1)] = lo;
            }
        }
    }
}

// ---------------------------------------------------------------------------
extern "C" void kernel_launch(void* const* d_in, const int* in_sizes, int n_in,
                              void* d_out, int out_size)
{
    const float* x  = (const float*)d_in[0];
    const float* Wq = (const float*)d_in[1];
    const float* bq = (const float*)d_in[2];
    const float* Wk = (const float*)d_in[3];
    const float* bk = (const float*)d_in[4];
    const float* Wv = (const float*)d_in[5];
    const float* bv = (const float*)d_in[6];
    const float* Wo = (const float*)d_in[7];
    const float* bo = (const float*)d_in[8];
    float* out = (float*)d_out;

    float *q_ptr, *k_ptr, *v_ptr;
    uint32_t *xh, *xl, *aoh, *aol, *wh, *wl;
    cudaGetSymbolAddress((void**)&q_ptr,  g_q);
    cudaGetSymbolAddress((void**)&k_ptr,  g_k);
    cudaGetSymbolAddress((void**)&v_ptr,  g_v);
    cudaGetSymbolAddress((void**)&xh,  g_xh);
    cudaGetSymbolAddress((void**)&xl,  g_xl);
    cudaGetSymbolAddress((void**)&aoh, g_aoh);
    cudaGetSymbolAddress((void**)&aol, g_aol);
    cudaGetSymbolAddress((void**)&wh,  g_wh);
    cudaGetSymbolAddress((void**)&wl,  g_wl);

    const int attn_smem = ATTN_SMEM_FLOATS * 4;
    static int attr_set = 0;
    if (!attr_set) {
        cudaFuncSetAttribute(attn_tf32,  cudaFuncAttributeMaxDynamicSharedMemorySize, attn_smem);
        cudaFuncSetAttribute(gemm_proj,  cudaFuncAttributeMaxDynamicSharedMemorySize, GEMM_SMEM_BYTES);
        cudaFuncSetAttribute(gemm_out,   cudaFuncAttributeMaxDynamicSharedMemorySize, GEMM_SMEM_BYTES);
        attr_set = 1;
    }

    // pre-split x and weights
    {
        const int npairs = MROWS * KPAIRS;                 // 4.19M
        split_pairs<<<(npairs + 255) / 256, 256>>>(x, xh, xl, npairs);
        dim3 wgrid((KPAIRS * EMB) / 256, 4);               // (2048, 4)
        split_w<<<wgrid, 256>>>(Wq, Wk, Wv, Wo, wh, wl);
    }

    dim3 gblk(256);
    dim3 pgrid(EMB / 128, MROWS / 128, 3);   // (8, 64, 3)
    gemm_proj<<<pgrid, gblk, GEMM_SMEM_BYTES>>>(xh, xl, wh, wl, bq, bk, bv,
                                                q_ptr, k_ptr, v_ptr);

    dim3 agrid(SEQ / 128, BATCH * HEADS);    // (16, 64)
    attn_tf32<<<agrid, 128, attn_smem>>>(q_ptr, k_ptr, v_ptr, aoh, aol);

    dim3 ogrid(EMB / 128, MROWS / 128, 1);   // (8, 64)
    gemm_out<<<ogrid, gblk, GEMM_SMEM_BYTES>>>(aoh, aol, wh, wl, bo, out);
}

// round 16
// speedup vs baseline: 1.1457x; 1.0181x over previous
#include <cuda_runtime.h>
#include <cuda_bf16.h>
#include <cstdint>
#include <cmath>

#define BATCH 4
#define SEQ   2048
#define EMB   1024
#define HEADS 16
#define HDIM  64
#define MROWS (BATCH*SEQ)   // 8192
#define KPAIRS (EMB/2)      // 512

// Scratch (no allocations allowed)
__device__ float g_q[BATCH*HEADS*SEQ*HDIM];
__device__ float g_k[BATCH*HEADS*SEQ*HDIM];
__device__ float g_v[BATCH*HEADS*SEQ*HDIM];
// pre-split bf16 hi/lo planes (packed pairs as u32)
__device__ uint32_t g_xh[MROWS*KPAIRS],  g_xl[MROWS*KPAIRS];    // x   [m][k/2]
__device__ uint32_t g_aoh[MROWS*KPAIRS], g_aol[MROWS*KPAIRS];   // ao  [m][k/2]
__device__ uint32_t g_wh[4*KPAIRS*EMB],  g_wl[4*KPAIRS*EMB];    // W   [k/2][n] x4

// ---------------------------------------------------------------------------
// helpers
// ---------------------------------------------------------------------------
__device__ __forceinline__ uint32_t tf32_rna(float x) {
    uint32_t r;
    asm("cvt.rna.tf32.f32 %0, %1;" : "=r"(r) : "f"(x));
    return r;
}
__device__ __forceinline__ float4 cvt4(float4 v) {
    v.x = __uint_as_float(tf32_rna(v.x));
    v.y = __uint_as_float(tf32_rna(v.y));
    v.z = __uint_as_float(tf32_rna(v.z));
    v.w = __uint_as_float(tf32_rna(v.w));
    return v;
}
__device__ __forceinline__ void mma_tf32(float* c, const uint32_t* a, const uint32_t* b) {
    asm volatile(
        "mma.sync.aligned.m16n8k8.row.col.f32.tf32.tf32.f32 "
        "{%0,%1,%2,%3}, {%4,%5,%6,%7}, {%8,%9}, {%0,%1,%2,%3};"
        : "+f"(c[0]), "+f"(c[1]), "+f"(c[2]), "+f"(c[3])
        : "r"(a[0]), "r"(a[1]), "r"(a[2]), "r"(a[3]), "r"(b[0]), "r"(b[1]));
}
__device__ __forceinline__ void mma_bf16(float* c, const uint32_t* a, const uint32_t* b) {
    asm volatile(
        "mma.sync.aligned.m16n8k16.row.col.f32.bf16.bf16.f32 "
        "{%0,%1,%2,%3}, {%4,%5,%6,%7}, {%8,%9}, {%0,%1,%2,%3};"
        : "+f"(c[0]), "+f"(c[1]), "+f"(c[2]), "+f"(c[3])
        : "r"(a[0]), "r"(a[1]), "r"(a[2]), "r"(a[3]), "r"(b[0]), "r"(b[1]));
}
__device__ __forceinline__ void bf16split2(float x0, float x1, uint32_t& hi, uint32_t& lo) {
    __nv_bfloat16 h0 = __float2bfloat16_rn(x0);
    __nv_bfloat16 h1 = __float2bfloat16_rn(x1);
    float r0 = x0 - __bfloat162float(h0);
    float r1 = x1 - __bfloat162float(h1);
    __nv_bfloat16 l0 = __float2bfloat16_rn(r0);
    __nv_bfloat16 l1 = __float2bfloat16_rn(r1);
    hi = ((uint32_t)__bfloat16_as_ushort(h1) << 16) | (uint32_t)__bfloat16_as_ushort(h0);
    lo = ((uint32_t)__bfloat16_as_ushort(l1) << 16) | (uint32_t)__bfloat16_as_ushort(l0);
}

// ---------------------------------------------------------------------------
// pre-split kernels
// ---------------------------------------------------------------------------
__global__ __launch_bounds__(256)
void split_pairs(const float* __restrict__ src, uint32_t* __restrict__ hp,
                 uint32_t* __restrict__ lp, int n_pairs)
{
    int i = blockIdx.x * blockDim.x + threadIdx.x;
    if (i >= n_pairs) return;
    const float2 v = ((const float2*)src)[i];
    uint32_t h, l;
    bf16split2(v.x, v.y, h, l);
    hp[i] = h; lp[i] = l;
}

__global__ __launch_bounds__(256)
void split_w(const float* __restrict__ W0, const float* __restrict__ W1,
             const float* __restrict__ W2, const float* __restrict__ W3,
             uint32_t* __restrict__ hp, uint32_t* __restrict__ lp)
{
    const int z = blockIdx.y;
    const float* W = (z == 0) ? W0 : (z == 1) ? W1 : (z == 2) ? W2 : W3;
    int i = blockIdx.x * blockDim.x + threadIdx.x;
    const int kp = i >> 10, n = i & (EMB - 1);
    const float a = W[((size_t)(2*kp))   * EMB + n];
    const float b = W[((size_t)(2*kp+1)) * EMB + n];
    uint32_t h, l;
    bf16split2(a, b, h, l);
    hp[(size_t)z * KPAIRS * EMB + i] = h;
    lp[(size_t)z * KPAIRS * EMB + i] = l;
}

// ---------------------------------------------------------------------------
// 3xBF16 GEMM body reading pre-split planes. Tile 128x128x16, 256 thr, 8 warps.
// ---------------------------------------------------------------------------
#define GSTG 5248
#define SAh(st,r,p) smu[(st)*GSTG          + (r)*12  + (p)]
#define SAl(st,r,p) smu[(st)*GSTG + 1536   + (r)*12  + (p)]
#define SBh(st,p,c) smu[(st)*GSTG + 3072   + (p)*136 + (c)]
#define SBl(st,p,c) smu[(st)*GSTG + 4160   + (p)*136 + (c)]
#define GEMM_SMEM_BYTES (2*GSTG*4)

__device__ __forceinline__ void gemm_body(
    const uint32_t* __restrict__ Ah, const uint32_t* __restrict__ Al,
    const uint32_t* __restrict__ Bh, const uint32_t* __restrict__ Bl,
    const float* __restrict__ bias, float* __restrict__ C,
    int headsplit, uint32_t* smu)
{
    const int N = EMB;
    const int tid  = threadIdx.x;
    const int wid  = tid >> 5;
    const int lane = tid & 31;
    const int gid  = lane >> 2;
    const int tig  = lane & 3;
    const int wm   = wid >> 1;
    const int wn   = wid & 1;
    const int row0 = blockIdx.y * 128;
    const int col0 = blockIdx.x * 128;

    float c[2][8][4];
#pragma unroll
    for (int mt = 0; mt < 2; mt++)
#pragma unroll
        for (int nt = 0; nt < 8; nt++)
#pragma unroll
            for (int i = 0; i < 4; i++) c[mt][nt][i] = 0.f;

    const int ar = tid >> 1, apo = (tid & 1) * 4;
    const int bp = tid >> 5, bc4 = (tid & 31) * 4;

    const uint32_t* Ahb = Ah + (size_t)(row0 + ar) * KPAIRS + apo;
    const uint32_t* Alb = Al + (size_t)(row0 + ar) * KPAIRS + apo;
    const uint32_t* Bhb = Bh + (size_t)bp * N + col0 + bc4;
    const uint32_t* Blb = Bl + (size_t)bp * N + col0 + bc4;

    uint4 a_h = *(const uint4*)(Ahb);
    uint4 a_l = *(const uint4*)(Alb);
    uint4 b_h = *(const uint4*)(Bhb);
    uint4 b_l = *(const uint4*)(Blb);

    *(uint4*)&SAh(0, ar, apo) = a_h;
    *(uint4*)&SAl(0, ar, apo) = a_l;
    *(uint4*)&SBh(0, bp, bc4) = b_h;
    *(uint4*)&SBl(0, bp, bc4) = b_l;
    __syncthreads();

    int cur = 0;
    for (int kp0 = 0; kp0 < KPAIRS; kp0 += 8) {
        const bool more = (kp0 + 8 < KPAIRS);
        if (more) {
            a_h = *(const uint4*)(Ahb + kp0 + 8);
            a_l = *(const uint4*)(Alb + kp0 + 8);
            b_h = *(const uint4*)(Bhb + (size_t)(kp0 + 8) * N);
            b_l = *(const uint4*)(Blb + (size_t)(kp0 + 8) * N);
        }

        uint32_t ahi[2][4], alo[2][4];
#pragma unroll
        for (int mt = 0; mt < 2; mt++) {
            const int m0 = wm * 32 + mt * 16;
            ahi[mt][0] = SAh(cur, m0 + gid,     tig);
            ahi[mt][1] = SAh(cur, m0 + gid + 8, tig);
            ahi[mt][2] = SAh(cur, m0 + gid,     tig + 4);
            ahi[mt][3] = SAh(cur, m0 + gid + 8, tig + 4);
            alo[mt][0] = SAl(cur, m0 + gid,     tig);
            alo[mt][1] = SAl(cur, m0 + gid + 8, tig);
            alo[mt][2] = SAl(cur, m0 + gid,     tig + 4);
            alo[mt][3] = SAl(cur, m0 + gid + 8, tig + 4);
        }
#pragma unroll
        for (int nt = 0; nt < 8; nt++) {
            const int n0 = wn * 64 + nt * 8;
            uint32_t bh[2], bl[2];
            bh[0] = SBh(cur, tig,     n0 + gid);
            bh[1] = SBh(cur, tig + 4, n0 + gid);
            bl[0] = SBl(cur, tig,     n0 + gid);
            bl[1] = SBl(cur, tig + 4, n0 + gid);
#pragma unroll
            for (int mt = 0; mt < 2; mt++) {
                mma_bf16(c[mt][nt], ahi[mt], bh);
                mma_bf16(c[mt][nt], alo[mt], bh);
                mma_bf16(c[mt][nt], ahi[mt], bl);
            }
        }

        if (more) {
            const int nxt = cur ^ 1;
            *(uint4*)&SAh(nxt, ar, apo) = a_h;
            *(uint4*)&SAl(nxt, ar, apo) = a_l;
            *(uint4*)&SBh(nxt, bp, bc4) = b_h;
            *(uint4*)&SBl(nxt, bp, bc4) = b_l;
            __syncthreads();
            cur = nxt;
        }
    }

#pragma unroll
    for (int mt = 0; mt < 2; mt++) {
        const int m_lo = row0 + wm * 32 + mt * 16 + gid;
        const int m_hi = m_lo + 8;
#pragma unroll
        for (int nt = 0; nt < 8; nt++) {
            const int n = col0 + wn * 64 + nt * 8 + 2 * tig;
            const float b0 = bias[n], b1 = bias[n + 1];
            float v00 = c[mt][nt][0] + b0, v01 = c[mt][nt][1] + b1;
            float v10 = c[mt][nt][2] + b0, v11 = c[mt][nt][3] + b1;
            if (headsplit) {
                const int b_lo = m_lo / SEQ, s_lo = m_lo % SEQ;
                const int b_hi = m_hi / SEQ, s_hi = m_hi % SEQ;
                const int h = n / HDIM, d = n % HDIM;
                C[(((size_t)(b_lo*HEADS + h))*SEQ + s_lo)*HDIM + d    ] = v00;
                C[(((size_t)(b_lo*HEADS + h))*SEQ + s_lo)*HDIM + d + 1] = v01;
                C[(((size_t)(b_hi*HEADS + h))*SEQ + s_hi)*HDIM + d    ] = v10;
                C[(((size_t)(b_hi*HEADS + h))*SEQ + s_hi)*HDIM + d + 1] = v11;
            } else {
                C[(size_t)m_lo * N + n    ] = v00;
                C[(size_t)m_lo * N + n + 1] = v01;
                C[(size_t)m_hi * N + n    ] = v10;
                C[(size_t)m_hi * N + n + 1] = v11;
            }
        }
    }
}

__global__ __launch_bounds__(256)
void gemm_proj(const uint32_t* __restrict__ Ah, const uint32_t* __restrict__ Al,
               const uint32_t* __restrict__ Wh, const uint32_t* __restrict__ Wl,
               const float* __restrict__ b0, const float* __restrict__ b1,
               const float* __restrict__ b2,
               float* __restrict__ C0, float* __restrict__ C1, float* __restrict__ C2)
{
    extern __shared__ __align__(16) uint32_t smu[];
    const int z = blockIdx.z;
    const float* b = (z == 0) ? b0 : (z == 1) ? b1 : b2;
    float*       C = (z == 0) ? C0 : (z == 1) ? C1 : C2;
    gemm_body(Ah, Al, Wh + (size_t)z * KPAIRS * EMB, Wl + (size_t)z * KPAIRS * EMB,
              b, C, 1, smu);
}

__global__ __launch_bounds__(256)
void gemm_out(const uint32_t* __restrict__ Ah, const uint32_t* __restrict__ Al,
              const uint32_t* __restrict__ Wh, const uint32_t* __restrict__ Wl,
              const float* __restrict__ b, float* __restrict__ C)
{
    extern __shared__ __align__(16) uint32_t smu[];
    gemm_body(Ah, Al, Wh + (size_t)3 * KPAIRS * EMB, Wl + (size_t)3 * KPAIRS * EMB,
              b, C, 0, smu);
}

// ---------------------------------------------------------------------------
// Causal flash attention v6: single-pass TF32, exp2 softmax, Q frags from SMEM
// (low regs -> 3 blocks/SM), work-descending order, mask fast-path,
// fused ao bf16-split epilogue.
// Block: 128 q-rows, 128 threads, 4 warps; warp owns 32 rows (2 m-tiles).
// ---------------------------------------------------------------------------
#define QS(r,c)    sQ[(r)*68 + (c)]
#define KS_(r,c)   sK[(r)*68 + (c)]
#define VS_(r,c)   sV[(r)*72 + (c)]
#define SSW(cc,rr) sP[(cc)*40 + (rr)]

#define ATTN_SMEM_FLOATS (128*68 + 32*68 + 32*72 + 4*32*40)
#define QSCALE (0.125f * 1.44269504088896340736f)   // 1/sqrt(D) * log2(e)

__global__ __launch_bounds__(128, 3)
void attn_tf32(const float* __restrict__ Q, const float* __restrict__ Kg,
               const float* __restrict__ Vg,
               uint32_t* __restrict__ AOh, uint32_t* __restrict__ AOl)
{
    extern __shared__ __align__(16) float smem[];
    float* sQ  = smem;                 // 128 x 68
    float* sK  = sQ + 128*68;          // 32 x 68
    float* sV  = sK + 32*68;           // 32 x 72
    float* sPb = sV + 32*72;           // 4 warps x (32 cols x 40)

    const int bh  = blockIdx.y;
    const int qt  = (gridDim.x - 1) - blockIdx.x;   // big-work blocks first
    const int tid = threadIdx.x;
    const int wid = tid >> 5;
    const int lane = tid & 31;
    const int gid = lane >> 2;
    const int tig = lane & 3;
    const int m0  = wid * 32;
    float* sP = sPb + wid * (32*40);

    const float* Qbase = Q + ((size_t)bh * SEQ + qt * 128) * HDIM;
    const float* Kbase = Kg + (size_t)bh * SEQ * HDIM;
    const float* Vbase = Vg + (size_t)bh * SEQ * HDIM;

    // stage Q (128x64), scaled by 1/sqrt(D)*log2e, cvt to tf32
    {
        const float* qr = Qbase + (size_t)tid * HDIM;
#pragma unroll
        for (int i = 0; i < 16; i++) {
            float4 v = *(const float4*)(qr + i * 4);
            v.x *= QSCALE; v.y *= QSCALE; v.z *= QSCALE; v.w *= QSCALE;
            *(float4*)&QS(tid, i * 4) = cvt4(v);
        }
    }
    __syncthreads();

    float o[2][8][4];
#pragma unroll
    for (int mt = 0; mt < 2; mt++)
#pragma unroll
        for (int nt = 0; nt < 8; nt++)
#pragma unroll
            for (int i = 0; i < 4; i++) o[mt][nt][i] = 0.f;
    float mrow[2][2] = {{-INFINITY,-INFINITY},{-INFINITY,-INFINITY}};
    float lrow[2][2] = {{0.f,0.f},{0.f,0.f}};

    const int qmax_warp = qt * 128 + m0 + 31;
    const int qmin_warp = qt * 128 + m0;
    const int nch = 4 * qt + 4;

    for (int ch = 0; ch < nch; ch++) {
        // stage K,V chunk (32x64), cvt to tf32
        {
            const int kr = tid >> 2, kc = (tid & 3) * 16;
            const float* kp = Kbase + (size_t)(ch * 32 + kr) * HDIM + kc;
            const float* vp = Vbase + (size_t)(ch * 32 + kr) * HDIM + kc;
#pragma unroll
            for (int i = 0; i < 4; i++) {
                *(float4*)&KS_(kr, kc + i * 4) = cvt4(*(const float4*)(kp + i * 4));
                *(float4*)&VS_(kr, kc + i * 4) = cvt4(*(const float4*)(vp + i * 4));
            }
        }
        __syncthreads();

        if (ch * 32 <= qmax_warp) {
            const bool needmask = (ch * 32 + 31 > qmin_warp);

            // ---- S = Q K^T : 32 rows x 32 keys per warp ----
            float s[2][4][4];
#pragma unroll
            for (int mt = 0; mt < 2; mt++)
#pragma unroll
                for (int nt = 0; nt < 4; nt++)
#pragma unroll
                    for (int i = 0; i < 4; i++) s[mt][nt][i] = 0.f;

#pragma unroll
            for (int ks = 0; ks < 8; ks++) {
                uint32_t a[2][4];
#pragma unroll
                for (int mt = 0; mt < 2; mt++) {
                    const int r0 = m0 + mt * 16;
                    a[mt][0] = __float_as_uint(QS(r0 + gid,     ks*8 + tig));
                    a[mt][1] = __float_as_uint(QS(r0 + gid + 8, ks*8 + tig));
                    a[mt][2] = __float_as_uint(QS(r0 + gid,     ks*8 + tig + 4));
                    a[mt][3] = __float_as_uint(QS(r0 + gid + 8, ks*8 + tig + 4));
                }
#pragma unroll
                for (int nt = 0; nt < 4; nt++) {
                    uint32_t b[2];
                    b[0] = __float_as_uint(KS_(nt*8 + gid, ks*8 + tig));
                    b[1] = __float_as_uint(KS_(nt*8 + gid, ks*8 + tig + 4));
                    mma_tf32(s[0][nt], a[0], b);
                    mma_tf32(s[1][nt], a[1], b);
                }
            }

            // ---- register online softmax (log2 domain) ----
#pragma unroll
            for (int mt = 0; mt < 2; mt++) {
#pragma unroll
                for (int half = 0; half < 2; half++) {
                    const int qrow = qt * 128 + m0 + mt * 16 + gid + half * 8;
                    const int cb   = ch * 32 + 2 * tig;
                    float mx = -INFINITY;
                    if (needmask) {
#pragma unroll
                        for (int nt = 0; nt < 4; nt++)
#pragma unroll
                            for (int ii = 0; ii < 2; ii++) {
                                const int cc = cb + nt * 8 + ii;
                                if (cc <= qrow)
                                    mx = fmaxf(mx, s[mt][nt][half * 2 + ii]);
                            }
                    } else {
#pragma unroll
                        for (int nt = 0; nt < 4; nt++)
#pragma unroll
                            for (int ii = 0; ii < 2; ii++)
                                mx = fmaxf(mx, s[mt][nt][half * 2 + ii]);
                    }
                    mx = fmaxf(mx, __shfl_xor_sync(0xffffffffu, mx, 1));
                    mx = fmaxf(mx, __shfl_xor_sync(0xffffffffu, mx, 2));
                    const float mold = mrow[mt][half];
                    const float mnew = fmaxf(mold, mx);
                    const float msafe = (mnew == -INFINITY) ? 0.f : mnew;
                    const float corr  = (mold == -INFINITY) ? 0.f : exp2f(mold - msafe);
                    float sum = 0.f;
                    if (needmask) {
#pragma unroll
                        for (int nt = 0; nt < 4; nt++)
#pragma unroll
                            for (int ii = 0; ii < 2; ii++) {
                                const int cc = cb + nt * 8 + ii;
                                float p = (cc <= qrow) ? exp2f(s[mt][nt][half*2+ii] - msafe) : 0.f;
                                s[mt][nt][half*2+ii] = p;
                                sum += p;
                            }
                    } else {
#pragma unroll
                        for (int nt = 0; nt < 4; nt++)
#pragma unroll
                            for (int ii = 0; ii < 2; ii++) {
                                float p = exp2f(s[mt][nt][half*2+ii] - msafe);
                                s[mt][nt][half*2+ii] = p;
                                sum += p;
                            }
                    }
                    sum += __shfl_xor_sync(0xffffffffu, sum, 1);
                    sum += __shfl_xor_sync(0xffffffffu, sum, 2);
                    lrow[mt][half] = lrow[mt][half] * corr + sum;
                    mrow[mt][half] = mnew;
#pragma unroll
                    for (int nt = 0; nt < 8; nt++) {
                        o[mt][nt][half*2+0] *= corr;
                        o[mt][nt][half*2+1] *= corr;
                    }
                }
            }

            // ---- write P (tf32-cvt'd) to per-warp buffer [col][row] stride 40 ----
#pragma unroll
            for (int mt = 0; mt < 2; mt++) {
                const int rl = mt * 16 + gid;
#pragma unroll
                for (int nt = 0; nt < 4; nt++) {
                    const int cc = nt * 8 + 2 * tig;
                    SSW(cc,     rl)     = __uint_as_float(tf32_rna(s[mt][nt][0]));
                    SSW(cc + 1, rl)     = __uint_as_float(tf32_rna(s[mt][nt][1]));
                    SSW(cc,     rl + 8) = __uint_as_float(tf32_rna(s[mt][nt][2]));
                    SSW(cc + 1, rl + 8) = __uint_as_float(tf32_rna(s[mt][nt][3]));
                }
            }
            __syncwarp();

            // ---- O += P V ----
#pragma unroll
            for (int ks = 0; ks < 4; ks++) {
                uint32_t p[2][4];
#pragma unroll
                for (int mt = 0; mt < 2; mt++) {
                    const int rl = mt * 16 + gid;
                    p[mt][0] = __float_as_uint(SSW(ks*8 + tig,     rl));
                    p[mt][1] = __float_as_uint(SSW(ks*8 + tig,     rl + 8));
                    p[mt][2] = __float_as_uint(SSW(ks*8 + tig + 4, rl));
                    p[mt][3] = __float_as_uint(SSW(ks*8 + tig + 4, rl + 8));
                }
#pragma unroll
                for (int nt = 0; nt < 8; nt++) {
                    uint32_t v[2];
                    v[0] = __float_as_uint(VS_(ks*8 + tig,     nt*8 + gid));
                    v[1] = __float_as_uint(VS_(ks*8 + tig + 4, nt*8 + gid));
                    mma_tf32(o[0][nt], p[0], v);
                    mma_tf32(o[1][nt], p[1], v);
                }
            }
        }
        __syncthreads();
    }

    // epilogue: normalize and write bf16 hi/lo planes directly
    const int b = bh / HEADS, h = bh % HEADS;
#pragma unroll
    for (int mt = 0; mt < 2; mt++) {
#pragma unroll
        for (int half = 0; half < 2; half++) {
            const float inv = 1.f / lrow[mt][half];
            const int sg = qt * 128 + m0 + mt * 16 + gid + half * 8;
            const size_t rowbase = (size_t)(b * SEQ + sg) * KPAIRS + h * (HDIM/2);
#pragma unroll
            for (int nt = 0; nt < 8; nt++) {
                const int cc = nt * 8 + 2 * tig;
                uint32_t hi, lo;
                bf16split2(o[mt][nt][half*2+0] * inv, o[mt][nt][half*2+1] * inv, hi, lo);
                AOh[rowbase + (cc >> 1)] = hi;
                AOl[rowbase + (cc >> 1)] = lo;
            }
        }
    }
}

// ---------------------------------------------------------------------------
extern "C" void kernel_launch(void* const* d_in, const int* in_sizes, int n_in,
                              void* d_out, int out_size)
{
    const float* x  = (const float*)d_in[0];
    const float* Wq = (const float*)d_in[1];
    const float* bq = (const float*)d_in[2];
    const float* Wk = (const float*)d_in[3];
    const float* bk = (const float*)d_in[4];
    const float* Wv = (const float*)d_in[5];
    const float* bv = (const float*)d_in[6];
    const float* Wo = (const float*)d_in[7];
    const float* bo = (const float*)d_in[8];
    float* out = (float*)d_out;

    float *q_ptr, *k_ptr, *v_ptr;
    uint32_t *xh, *xl, *aoh, *aol, *wh, *wl;
    cudaGetSymbolAddress((void**)&q_ptr,  g_q);
    cudaGetSymbolAddress((void**)&k_ptr,  g_k);
    cudaGetSymbolAddress((void**)&v_ptr,  g_v);
    cudaGetSymbolAddress((void**)&xh,  g_xh);
    cudaGetSymbolAddress((void**)&xl,  g_xl);
    cudaGetSymbolAddress((void**)&aoh, g_aoh);
    cudaGetSymbolAddress((void**)&aol, g_aol);
    cudaGetSymbolAddress((void**)&wh,  g_wh);
    cudaGetSymbolAddress((void**)&wl,  g_wl);

    const int attn_smem = ATTN_SMEM_FLOATS * 4;
    static int attr_set = 0;
    if (!attr_set) {
        cudaFuncSetAttribute(attn_tf32,  cudaFuncAttributeMaxDynamicSharedMemorySize, attn_smem);
        cudaFuncSetAttribute(gemm_proj,  cudaFuncAttributeMaxDynamicSharedMemorySize, GEMM_SMEM_BYTES);
        cudaFuncSetAttribute(gemm_out,   cudaFuncAttributeMaxDynamicSharedMemorySize, GEMM_SMEM_BYTES);
        attr_set = 1;
    }

    // pre-split x and weights
    {
        const int npairs = MROWS * KPAIRS;                 // 4.19M
        split_pairs<<<(npairs + 255) / 256, 256>>>(x, xh, xl, npairs);
        dim3 wgrid((KPAIRS * EMB) / 256, 4);               // (2048, 4)
        split_w<<<wgrid, 256>>>(Wq, Wk, Wv, Wo, wh, wl);
    }

    dim3 gblk(256);
    dim3 pgrid(EMB / 128, MROWS / 128, 3);   // (8, 64, 3)
    gemm_proj<<<pgrid, gblk, GEMM_SMEM_BYTES>>>(xh, xl, wh, wl, bq, bk, bv,
                                                q_ptr, k_ptr, v_ptr);

    dim3 agrid(SEQ / 128, BATCH * HEADS);    // (16, 64)
    attn_tf32<<<agrid, 128, attn_smem>>>(q_ptr, k_ptr, v_ptr, aoh, aol);

    dim3 ogrid(EMB / 128, MROWS / 128, 1);   // (8, 64)
    gemm_out<<<ogrid, gblk, GEMM_SMEM_BYTES>>>(aoh, aol, wh, wl, bo, out);
}